// round 8
// baseline (speedup 1.0000x reference)
#include <cuda_runtime.h>
#include <cuda_fp16.h>
#include <math.h>
#include <stdint.h>

#define B_    128
#define L_    512
#define D_    128
#define H_    8
#define E_    16
#define DFF_  512
#define LP_   514

// ---------------- fp32 scratch ----------------
__device__ float g_MarkT[B_*L_*D_];
__device__ float g_H    [B_*L_*D_];
__device__ float g_T1   [B_*L_*D_];
__device__ float g_T2   [B_*L_*D_];
__device__ float g_F    [B_*D_*128];
__device__ float g_PE   [512*128];
__device__ float g_CM   [B_*D_];

// ---------------- fp16 activation scratch ----------------
__device__ __half g_X [B_*LP_*D_];
__device__ __half g_Hx[B_*L_*D_];
__device__ __half g_Q [B_*L_*D_];
__device__ __half g_QT[B_*L_*D_];
__device__ __half g_S [B_*D_*128];
__device__ __half g_U [B_*L_*DFF_];

// ---------------- fp16 weights, [N, K] row-major ----------------
__device__ __half g_cw[128*384];
__device__ __half g_fb[128*512];
__device__ __half g_ib[512*128];
__device__ __half g_wq[2*128*128];
__device__ __half g_wo[2*128*128];
__device__ __half g_w1[2*512*128];
__device__ __half g_w2[2*128*512];

__device__ __forceinline__ float geluf(float v) {
    return 0.5f * v * (1.0f + erff(v * 0.7071067811865476f));
}
__device__ __forceinline__ uint32_t pack2h(__half a, __half b) {
    return (uint32_t)__half_as_ushort(a) | ((uint32_t)__half_as_ushort(b) << 16);
}
__device__ __forceinline__ uint32_t smem_u32(const void* p) {
    uint32_t a;
    asm("{ .reg .u64 t; cvta.to.shared.u64 t, %1; cvt.u32.u64 %0, t; }" : "=r"(a) : "l"(p));
    return a;
}
__device__ __forceinline__ void ldsm4(uint32_t* r, uint32_t a) {
    asm volatile("ldmatrix.sync.aligned.m8n8.x4.shared.b16 {%0,%1,%2,%3}, [%4];"
        : "=r"(r[0]), "=r"(r[1]), "=r"(r[2]), "=r"(r[3]) : "r"(a));
}
__device__ __forceinline__ void mma16816(float* c, const uint32_t* a, const uint32_t* b) {
    asm volatile(
        "mma.sync.aligned.m16n8k16.row.col.f32.f16.f16.f32 "
        "{%0,%1,%2,%3}, {%4,%5,%6,%7}, {%8,%9}, {%0,%1,%2,%3};"
        : "+f"(c[0]), "+f"(c[1]), "+f"(c[2]), "+f"(c[3])
        : "r"(a[0]), "r"(a[1]), "r"(a[2]), "r"(a[3]), "r"(b[0]), "r"(b[1]));
}
#define CP16(d, s)   asm volatile("cp.async.cg.shared.global [%0], [%1], 16;" :: "r"(d), "l"(s))
#define CPCOMMIT()   asm volatile("cp.async.commit_group;" ::: "memory")
#define CPWAIT1()    asm volatile("cp.async.wait_group 1;" ::: "memory")

// 128B rows (64 halves) = 8 x 16B chunks; SW128: chunk ^= row&7
__device__ __forceinline__ uint32_t sw64(int row, int ch) {
    return (uint32_t)(row * 128) + (uint32_t)(((ch ^ (row & 7)) << 4));
}

// ---------------- prep: weights -> fp16 [N,K]; PE table; zero CM -----------
__global__ void k_prep(const float* __restrict__ conv_w, const float* __restrict__ Wq,
                       const float* __restrict__ Wo, const float* __restrict__ W1,
                       const float* __restrict__ W2) {
    int idx = blockIdx.x * 256 + threadIdx.x;   // 65536 total
    if (idx < 49152) {
        int n = idx / 384, k = idx - n*384;
        int s = k >> 7, din = k & 127;
        g_cw[idx] = __float2half_rn(conv_w[n*384 + din*3 + s]);
    }
    if (idx < B_*D_) g_CM[idx] = 0.f;
    {   // forward DFT basis: N=128 (coeff), K=512 (t)
        int n = idx >> 9, t = idx & 511, m = n & 63;
        float x = (float)(m * t) * (1.0f/256.0f);
        float v = (n < 64) ? cospif(x) : -sinpif(x);
        g_fb[idx] = __float2half_rn(v);
    }
    {   // inverse DFT basis: N=512 (t), K=128 (coeff)
        int t = idx >> 7, n = idx & 127, m = n & 63;
        float x = (float)(m * t) * (1.0f/256.0f);
        float v;
        if (n == 0)       v = 1.0f/512.0f;
        else if (n < 64)  v = cospif(x) * (2.0f/512.0f);
        else if (n == 64) v = 0.0f;
        else              v = -sinpif(x) * (2.0f/512.0f);
        g_ib[idx] = __float2half_rn(v);
    }
    #pragma unroll
    for (int ly = 0; ly < 2; ly++) {
        if (idx < 16384) {
            int n = idx >> 7, k = idx & 127;
            g_wq[ly*16384 + idx] = __float2half_rn(Wq[ly*16384 + k*128 + n]);
            g_wo[ly*16384 + idx] = __float2half_rn(Wo[ly*16384 + k*128 + n]);
        }
        {
            int n = idx >> 7, k = idx & 127;
            g_w1[ly*65536 + idx] = __float2half_rn(W1[ly*65536 + k*512 + n]);
        }
        {
            int n = idx >> 9, k = idx & 511;
            g_w2[ly*65536 + idx] = __float2half_rn(W2[ly*65536 + k*128 + n]);
        }
    }
    {
        int t = idx >> 7, d = idx & 127;
        int i2 = d & ~1;
        float div = expf((float)i2 * (-9.210340371976184f / 128.0f));
        float a = (float)t * div;
        g_PE[idx] = (d & 1) ? cosf(a) : sinf(a);
    }
}

// ---------------- input transpose ----------------
__global__ void k_transpose(const float* __restrict__ x_enc,
                            const float* __restrict__ mark) {
    __shared__ float tile [32][33];
    __shared__ float tileM[32][33];
    int b = blockIdx.z;
    int d0 = blockIdx.y * 32, l0 = blockIdx.x * 32;
    int tx = threadIdx.x, ty = threadIdx.y;
    const float* xb = x_enc + b*65536;
    const float* mb = mark  + b*65536;
    #pragma unroll
    for (int i = ty; i < 32; i += 8) {
        tile [i][tx] = xb[(d0+i)*512 + l0 + tx];
        tileM[i][tx] = mb[(d0+i)*512 + l0 + tx];
    }
    __syncthreads();
    float* mo = g_MarkT + b*65536;
    #pragma unroll
    for (int i = ty; i < 32; i += 8) {
        int oi = b*LP_*128 + (l0+i+1)*128 + d0+tx;
        g_X[oi] = __float2half_rn(tile[tx][i]);
        mo[(l0+i)*128 + d0+tx] = tileM[tx][i];
    }
}
__global__ void k_edges(const float* __restrict__ x_enc) {
    int idx = blockIdx.x*256 + threadIdx.x;
    if (idx < B_*D_) {
        int b = idx >> 7, d = idx & 127;
        g_X[b*LP_*128 + d] = __float2half_rn(x_enc[b*65536 + d*512 + 511]);
        g_X[b*LP_*128 + 513*128 + d] = __float2half_rn(x_enc[b*65536 + d*512]);
    }
}

// ---------------- fp16 transpose (b,l,d) -> (b,d,l) ----------------
__global__ void k_tq() {
    __shared__ __half th[32][34];
    int b = blockIdx.z;
    int l0 = blockIdx.x * 32, d0 = blockIdx.y * 32;
    int tx = threadIdx.x, ty = threadIdx.y;
    #pragma unroll
    for (int i = ty; i < 32; i += 8)
        th[i][tx] = g_Q[b*65536 + (l0+i)*128 + d0 + tx];
    __syncthreads();
    #pragma unroll
    for (int i = ty; i < 32; i += 8)
        g_QT[b*65536 + (d0+i)*512 + l0 + tx] = th[tx][i];
}

// ---------------- fp16 HMMA GEMM, cp.async 3-stage, K-chunk 64 --------------
// CTA tile 64(M) x 128(N); 8 warps of 32x32; 3 CTAs/SM.
// A(row,k) = A[(row>>absh)*abstr + (row&mask)*arstr + k]
// EPI bits: 1=+bias[col], 2=+res, 4=gelu, 8=+PE, 16=skip fp32 C store
// WRB: also write fp16 result to Cf
// SMEM/stage (24KB): A@0(8K) B@8K(16K); 3 stages = 72KB.
template<int EPI, int WRB>
__global__ void __launch_bounds__(256, 3) k_tgemm(
    const __half* __restrict__ A, const __half* __restrict__ B,
    const float* __restrict__ bias, const float* __restrict__ res,
    float* __restrict__ C, __half* __restrict__ Cf,
    int K, int ldc, int absh, int abstr, int arstr)
{
    extern __shared__ char sm[];
    const uint32_t sU = smem_u32(sm);
    const int tid = threadIdx.x, wid = tid >> 5, lane = tid & 31;
    const int rowBase = blockIdx.x * 64, colBase = blockIdx.y * 128;
    const int amask = (1 << absh) - 1;

    float acc[2][4][4];
    #pragma unroll
    for (int i = 0; i < 2; i++)
        #pragma unroll
        for (int j = 0; j < 4; j++)
            #pragma unroll
            for (int q = 0; q < 4; q++) acc[i][j][q] = 0.f;

    const int nc = K >> 6;

    // per-thread load geometry: row groups of (tid>>3), chunk = tid&7
    const int lrow = tid >> 3, lch = tid & 7;
    const uint32_t a_sw0 = sw64(lrow, lch),      a_sw1 = sw64(lrow + 32, lch);
    int a_rg0 = rowBase + lrow, a_rg1 = rowBase + lrow + 32;
    const long a_b0 = (long)(a_rg0 >> absh)*abstr + (long)(a_rg0 & amask)*arstr + lch*8;
    const long a_b1 = (long)(a_rg1 >> absh)*abstr + (long)(a_rg1 & amask)*arstr + lch*8;
    const long b_b0 = (long)(colBase + lrow      )*K + lch*8;
    const long b_b1 = (long)(colBase + lrow + 32 )*K + lch*8;
    const long b_b2 = (long)(colBase + lrow + 64 )*K + lch*8;
    const long b_b3 = (long)(colBase + lrow + 96 )*K + lch*8;
    const uint32_t b_sw0 = sw64(lrow, lch),      b_sw1 = sw64(lrow + 32, lch);
    const uint32_t b_sw2 = sw64(lrow + 64, lch), b_sw3 = sw64(lrow + 96, lch);

    auto load_chunk = [&](int stage, int k0) {
        uint32_t sb = sU + stage * 24576;
        CP16(sb + a_sw0, A + a_b0 + k0);
        CP16(sb + a_sw1, A + a_b1 + k0);
        uint32_t bb = sb + 8192;
        CP16(bb + b_sw0, B + b_b0 + k0);
        CP16(bb + b_sw1, B + b_b1 + k0);
        CP16(bb + b_sw2, B + b_b2 + k0);
        CP16(bb + b_sw3, B + b_b3 + k0);
    };

    load_chunk(0, 0);  CPCOMMIT();
    load_chunk(1, 64); CPCOMMIT();

    const int mrow = (wid & 1) * 32;
    const int ncol = (wid >> 1) * 32;
    const int a_lr  = mrow + (lane & 15);
    const int a_lc  = lane >> 4;
    const int b_lr  = ncol + (lane & 7) + ((lane & 16) ? 8 : 0);
    const int b_lc  = (lane >> 3) & 1;
    int stage = 0;

    for (int c = 0; c < nc; c++) {
        CPWAIT1();
        __syncthreads();
        if (c + 2 < nc) {
            int ns = stage + 2; if (ns >= 3) ns -= 3;
            load_chunk(ns, (c + 2) * 64);
        }
        CPCOMMIT();

        uint32_t sb = sU + stage * 24576;
        #pragma unroll
        for (int ks = 0; ks < 4; ks++) {
            uint32_t af[2][4], bf[2][4];
            #pragma unroll
            for (int g = 0; g < 2; g++) {
                int r = b_lr + g*16, ci = ks*2 + b_lc;
                ldsm4(bf[g], sb + 8192 + sw64(r, ci));
            }
            #pragma unroll
            for (int f = 0; f < 2; f++) {
                int r = a_lr + f*16, ci = ks*2 + a_lc;
                ldsm4(af[f], sb + sw64(r, ci));
            }
            #pragma unroll
            for (int mi = 0; mi < 2; mi++)
                #pragma unroll
                for (int ni = 0; ni < 4; ni++)
                    mma16816(acc[mi][ni], af[mi], &bf[ni >> 1][(ni & 1) * 2]);
        }
        if (++stage >= 3) stage -= 3;
    }

    // ---- epilogue ----
    #pragma unroll
    for (int mi = 0; mi < 2; mi++) {
        #pragma unroll
        for (int half = 0; half < 2; half++) {
            int grow = rowBase + mrow + mi*16 + (lane >> 2) + half*8;
            #pragma unroll
            for (int ni = 0; ni < 4; ni++) {
                int gcol = colBase + ncol + ni*8 + (lane & 3)*2;
                float v0 = acc[mi][ni][half*2 + 0];
                float v1 = acc[mi][ni][half*2 + 1];
                if (EPI & 1) { v0 += bias[gcol]; v1 += bias[gcol + 1]; }
                if (EPI & 8) {
                    int pbi = (grow & 511)*128 + (gcol & 127);
                    v0 += g_PE[pbi]; v1 += g_PE[pbi + 1];
                }
                long oidx = (long)grow * ldc + gcol;
                if (EPI & 2) {
                    float2 rr = *(const float2*)(res + oidx);
                    v0 += rr.x; v1 += rr.y;
                }
                if (EPI & 4) { v0 = geluf(v0); v1 = geluf(v1); }
                if (!(EPI & 16)) {
                    float2 o; o.x = v0; o.y = v1;
                    *(float2*)(C + oidx) = o;
                }
                if (WRB) {
                    *(uint32_t*)(Cf + oidx) =
                        pack2h(__float2half_rn(v0), __float2half_rn(v1));
                }
            }
        }
    }
}

// ---------------- complex mode mixing (fp32 in, fp16 out) ------------------
__global__ void k_mix(const float* __restrict__ fwr,
                      const float* __restrict__ fwi, int layer) {
    int b = blockIdx.x, hh = blockIdx.y;
    int m = threadIdx.x;
    const float* wr = fwr + (size_t)((layer*H_ + hh)*E_*E_) * 64;
    const float* wi = fwi + (size_t)((layer*H_ + hh)*E_*E_) * 64;
    float sr[E_], si[E_];
    #pragma unroll
    for (int o = 0; o < E_; o++) { sr[o] = 0.f; si[o] = 0.f; }
    const float* Fb = g_F + (b*128 + hh*16) * 128;
    #pragma unroll
    for (int e = 0; e < E_; e++) {
        float fre = Fb[e*128 + m];
        float fim = Fb[e*128 + 64 + m];
        #pragma unroll
        for (int o = 0; o < E_; o++) {
            float cr = wr[(e*E_ + o)*64 + m];
            float ci = wi[(e*E_ + o)*64 + m];
            sr[o] += fre*cr - fim*ci;
            si[o] += fre*ci + fim*cr;
        }
    }
    int base = (b*128 + hh*16) * 128;
    #pragma unroll
    for (int o = 0; o < E_; o++) {
        g_S[base + o*128 + m]      = __float2half_rn(sr[o]);
        g_S[base + o*128 + 64 + m] = __float2half_rn(si[o]);
    }
}

// ---------------- series_decomp: fp32 + fp16 outputs ------------------------
__global__ void k_movsub(const float* __restrict__ X, float* __restrict__ Out,
                         __half* __restrict__ Oh) {
    __shared__ float sh[88 * 128];
    int b = blockIdx.x, t0 = blockIdx.y * 64;
    int d = threadIdx.x;
    const float* Xb = X + b*65536;
    #pragma unroll 4
    for (int r = 0; r < 88; r++) {
        int t = t0 + r - 12;
        t = max(0, min(511, t));
        sh[r*128 + d] = Xb[t*128 + d];
    }
    float s = 0.f;
    #pragma unroll 4
    for (int r = 0; r < 88; r++) { s += sh[r*128 + d]; sh[r*128 + d] = s; }
    #pragma unroll 4
    for (int tt = 0; tt < 64; tt++) {
        int r = tt + 12;
        float hi = sh[(r+12)*128 + d];
        float lo = (r >= 13) ? sh[(r-13)*128 + d] : 0.f;
        float v = Xb[(t0+tt)*128 + d] - (hi - lo) * (1.0f/25.0f);
        int oi = b*65536 + (t0+tt)*128 + d;
        Out[oi] = v;
        Oh[oi] = __float2half_rn(v);
    }
}

// ---------------- LayerNorm + fused column-sum ------------------------------
__global__ void k_ln(const float* __restrict__ X, const float* __restrict__ g,
                     const float* __restrict__ be, float* __restrict__ Out) {
    __shared__ float cm[128];
    int row  = blockIdx.x*8 + (threadIdx.x >> 5);     // 8 rows per block, same b
    int lane = threadIdx.x & 31;
    if (threadIdx.x < 128) cm[threadIdx.x] = 0.f;
    __syncthreads();
    const float* xr = X + (size_t)row * 128;
    float v[4];
    float s = 0.f;
    #pragma unroll
    for (int i = 0; i < 4; i++) { v[i] = xr[lane + i*32]; s += v[i]; }
    #pragma unroll
    for (int o = 16; o > 0; o >>= 1) s += __shfl_xor_sync(0xffffffffu, s, o);
    float mu = s * (1.0f/128.0f);
    float q = 0.f;
    #pragma unroll
    for (int i = 0; i < 4; i++) { float dl = v[i] - mu; q += dl*dl; }
    #pragma unroll
    for (int o = 16; o > 0; o >>= 1) q += __shfl_xor_sync(0xffffffffu, q, o);
    float rstd = rsqrtf(q * (1.0f/128.0f) + 1e-5f);
    float* orow = Out + (size_t)row * 128;
    #pragma unroll
    for (int i = 0; i < 4; i++) {
        int d = lane + i*32;
        float o = (v[i] - mu) * rstd * g[d] + be[d];
        orow[d] = o;
        atomicAdd(&cm[d], o);
    }
    __syncthreads();
    if (threadIdx.x < 128) {
        int b = row >> 9;
        atomicAdd(&g_CM[b*128 + threadIdx.x], cm[threadIdx.x]);
    }
}

__global__ void k_final(const float* __restrict__ HN, const float* __restrict__ pw,
                        const float* __restrict__ pb, float* __restrict__ out) {
    int b = blockIdx.x, tid = threadIdx.x;
    const float* hb = HN + b*65536;
    const float* mb = g_MarkT + b*65536;
    float s = 0.f;
    for (int i = tid; i < 65536; i += 256) {
        float v = hb[i] - g_CM[b*128 + (i & 127)] * (1.0f/512.0f);
        s += geluf(v) * mb[i] * pw[i];
    }
    __shared__ float red[256];
    red[tid] = s; __syncthreads();
    #pragma unroll
    for (int o = 128; o > 0; o >>= 1) {
        if (tid < o) red[tid] += red[tid + o];
        __syncthreads();
    }
    if (tid == 0) out[b] = red[0] + pb[0];
}

// ---------------- host orchestration ----------------
#define SMB 73728

extern "C" void kernel_launch(void* const* d_in, const int* in_sizes, int n_in,
                              void* d_out, int out_size) {
    const float* x_enc  = (const float*)d_in[0];
    const float* mark   = (const float*)d_in[1];
    const float* conv_w = (const float*)d_in[4];
    const float* Wq     = (const float*)d_in[5];
    const float* bq     = (const float*)d_in[6];
    const float* Wo     = (const float*)d_in[7];
    const float* bo     = (const float*)d_in[8];
    const float* fwr    = (const float*)d_in[9];
    const float* fwi    = (const float*)d_in[10];
    const float* W1     = (const float*)d_in[11];
    const float* W2     = (const float*)d_in[12];
    const float* ln_g   = (const float*)d_in[13];
    const float* ln_b   = (const float*)d_in[14];
    const float* pw     = (const float*)d_in[15];
    const float* pb     = (const float*)d_in[16];
    float* out = (float*)d_out;

    cudaFuncSetAttribute(k_tgemm<8,1>,  cudaFuncAttributeMaxDynamicSharedMemorySize, SMB);
    cudaFuncSetAttribute(k_tgemm<17,1>, cudaFuncAttributeMaxDynamicSharedMemorySize, SMB);
    cudaFuncSetAttribute(k_tgemm<0,0>,  cudaFuncAttributeMaxDynamicSharedMemorySize, SMB);
    cudaFuncSetAttribute(k_tgemm<16,1>, cudaFuncAttributeMaxDynamicSharedMemorySize, SMB);
    cudaFuncSetAttribute(k_tgemm<3,0>,  cudaFuncAttributeMaxDynamicSharedMemorySize, SMB);
    cudaFuncSetAttribute(k_tgemm<20,1>, cudaFuncAttributeMaxDynamicSharedMemorySize, SMB);
    cudaFuncSetAttribute(k_tgemm<2,0>,  cudaFuncAttributeMaxDynamicSharedMemorySize, SMB);

    float *pH, *pT1, *pT2, *pF;
    cudaGetSymbolAddress((void**)&pH,   g_H);
    cudaGetSymbolAddress((void**)&pT1,  g_T1);
    cudaGetSymbolAddress((void**)&pT2,  g_T2);
    cudaGetSymbolAddress((void**)&pF,   g_F);
    __half *x16,*hx,*q16,*qt,*s16,*u16;
    cudaGetSymbolAddress((void**)&x16, g_X);
    cudaGetSymbolAddress((void**)&hx,  g_Hx);
    cudaGetSymbolAddress((void**)&q16, g_Q);
    cudaGetSymbolAddress((void**)&qt,  g_QT);
    cudaGetSymbolAddress((void**)&s16, g_S);
    cudaGetSymbolAddress((void**)&u16, g_U);
    __half *cw,*fb,*ib,*wq,*wo,*w1,*w2;
    cudaGetSymbolAddress((void**)&cw, g_cw);
    cudaGetSymbolAddress((void**)&fb, g_fb);
    cudaGetSymbolAddress((void**)&ib, g_ib);
    cudaGetSymbolAddress((void**)&wq, g_wq);
    cudaGetSymbolAddress((void**)&wo, g_wo);
    cudaGetSymbolAddress((void**)&w1, g_w1);
    cudaGetSymbolAddress((void**)&w2, g_w2);

    k_prep<<<256, 256>>>(conv_w, Wq, Wo, W1, W2);
    k_transpose<<<dim3(16,4,128), dim3(32,8)>>>(x_enc, mark);
    k_edges<<<64, 256>>>(x_enc);

    // TokenEmbedding conv (K=384) + PE -> fp32 H + fp16 H
    k_tgemm<8,1><<<dim3(1024,1), 256, SMB>>>(
        x16, cw, nullptr, nullptr, pH, hx, 384, 128, 9, LP_*128, 128);

    for (int l = 0; l < 2; l++) {
        // Q = H @ Wq + bq -> fp16
        k_tgemm<17,1><<<dim3(1024,1), 256, SMB>>>(
            hx, wq + l*16384, bq + l*128, nullptr, nullptr, q16,
            128, 128, 30, 0, 128);
        // transpose Q (b,l,d) -> (b,d,l)
        k_tq<<<dim3(16,4,128), dim3(32,8)>>>();
        // forward DFT -> fp32 F
        k_tgemm<0,0><<<dim3(256,1), 256, SMB>>>(
            qt, fb, nullptr, nullptr, pF, nullptr, 512, 128, 30, 0, 512);
        // complex mode mixing -> fp16 S
        k_mix<<<dim3(128,8), 64>>>(fwr, fwi, l);
        // inverse DFT -> fp16 flat (== scrambled view(B,L,-1))
        k_tgemm<16,1><<<dim3(256,4), 256, SMB>>>(
            s16, ib, nullptr, nullptr, nullptr, q16, 128, 512, 30, 0, 128);
        // out proj + bias + residual -> fp32 T2
        k_tgemm<3,0><<<dim3(1024,1), 256, SMB>>>(
            q16, wo + l*16384, bo + l*128, pH, pT2, nullptr,
            128, 128, 30, 0, 128);
        // decomp1 -> fp32 H + fp16 H
        k_movsub<<<dim3(128,8), 128>>>(pT2, pH, hx);
        // FFN up + gelu -> fp16 U
        k_tgemm<20,1><<<dim3(1024,4), 256, SMB>>>(
            hx, w1 + l*65536, nullptr, nullptr, nullptr, u16,
            128, 512, 30, 0, 128);
        // FFN down + residual -> fp32 T2
        k_tgemm<2,0><<<dim3(1024,1), 256, SMB>>>(
            u16, w2 + l*65536, nullptr, pH, pT2, nullptr,
            512, 128, 30, 0, 512);
        // decomp2 -> fp32 H + fp16 H
        k_movsub<<<dim3(128,8), 128>>>(pT2, pH, hx);
    }

    k_ln<<<8192, 256>>>(pH, ln_g, ln_b, pT1);
    k_final<<<128, 256>>>(pT1, pw, pb, out);
}

// round 9
// speedup vs baseline: 1.0094x; 1.0094x over previous
#include <cuda_runtime.h>
#include <cuda_fp16.h>
#include <math.h>
#include <stdint.h>

#define B_    128
#define L_    512
#define D_    128
#define H_    8
#define E_    16
#define DFF_  512
#define LP_   514

// ---------------- fp32 scratch ----------------
__device__ float g_MarkT[B_*L_*D_];
__device__ float g_H    [B_*L_*D_];
__device__ float g_T1   [B_*L_*D_];
__device__ float g_T2   [B_*L_*D_];
__device__ float g_F    [B_*D_*128];
__device__ float g_PE   [512*128];
__device__ float g_CM   [B_*D_];

// ---------------- fp16 activation scratch ----------------
__device__ __half g_X [B_*LP_*D_];
__device__ __half g_Hx[B_*L_*D_];
__device__ __half g_Q [B_*L_*D_];
__device__ __half g_QT[B_*L_*D_];
__device__ __half g_S [B_*D_*128];
__device__ __half g_U [B_*L_*DFF_];

// ---------------- fp16 weights, [N, K] row-major ----------------
__device__ __half g_cw[128*384];
__device__ __half g_fb[128*512];
__device__ __half g_ib[512*128];
__device__ __half g_wq[2*128*128];
__device__ __half g_wo[2*128*128];
__device__ __half g_w1[2*512*128];
__device__ __half g_w2[2*128*512];

__device__ __forceinline__ float geluf(float v) {
    return 0.5f * v * (1.0f + erff(v * 0.7071067811865476f));
}
__device__ __forceinline__ uint32_t pack2h(__half a, __half b) {
    return (uint32_t)__half_as_ushort(a) | ((uint32_t)__half_as_ushort(b) << 16);
}
__device__ __forceinline__ uint32_t smem_u32(const void* p) {
    uint32_t a;
    asm("{ .reg .u64 t; cvta.to.shared.u64 t, %1; cvt.u32.u64 %0, t; }" : "=r"(a) : "l"(p));
    return a;
}
__device__ __forceinline__ void ldsm4(uint32_t* r, uint32_t a) {
    asm volatile("ldmatrix.sync.aligned.m8n8.x4.shared.b16 {%0,%1,%2,%3}, [%4];"
        : "=r"(r[0]), "=r"(r[1]), "=r"(r[2]), "=r"(r[3]) : "r"(a));
}
__device__ __forceinline__ void mma16816(float* c, const uint32_t* a, const uint32_t* b) {
    asm volatile(
        "mma.sync.aligned.m16n8k16.row.col.f32.f16.f16.f32 "
        "{%0,%1,%2,%3}, {%4,%5,%6,%7}, {%8,%9}, {%0,%1,%2,%3};"
        : "+f"(c[0]), "+f"(c[1]), "+f"(c[2]), "+f"(c[3])
        : "r"(a[0]), "r"(a[1]), "r"(a[2]), "r"(a[3]), "r"(b[0]), "r"(b[1]));
}
#define CP16(d, s)   asm volatile("cp.async.cg.shared.global [%0], [%1], 16;" :: "r"(d), "l"(s))
#define CPCOMMIT()   asm volatile("cp.async.commit_group;" ::: "memory")
#define CPWAIT1()    asm volatile("cp.async.wait_group 1;" ::: "memory")

// tile row = 32 halves = 64B = 4x16B chunks; swizzle chunk ^= (row>>1)&3
__device__ __forceinline__ uint32_t sw32(int row, int ch) {
    return (uint32_t)(row * 64) + (uint32_t)(((ch ^ ((row >> 1) & 3)) << 4));
}

// ---------------- prep: weights -> fp16 [N,K]; PE table --------------------
__global__ void k_prep(const float* __restrict__ conv_w, const float* __restrict__ Wq,
                       const float* __restrict__ Wo, const float* __restrict__ W1,
                       const float* __restrict__ W2) {
    int idx = blockIdx.x * 256 + threadIdx.x;   // 65536 total
    if (idx < 49152) {
        int n = idx / 384, k = idx - n*384;
        int s = k >> 7, din = k & 127;
        g_cw[idx] = __float2half_rn(conv_w[n*384 + din*3 + s]);
    }
    {   // forward DFT basis: N=128 (coeff), K=512 (t)
        int n = idx >> 9, t = idx & 511, m = n & 63;
        float x = (float)(m * t) * (1.0f/256.0f);
        float v = (n < 64) ? cospif(x) : -sinpif(x);
        g_fb[idx] = __float2half_rn(v);
    }
    {   // inverse DFT basis: N=512 (t), K=128 (coeff)
        int t = idx >> 7, n = idx & 127, m = n & 63;
        float x = (float)(m * t) * (1.0f/256.0f);
        float v;
        if (n == 0)       v = 1.0f/512.0f;
        else if (n < 64)  v = cospif(x) * (2.0f/512.0f);
        else if (n == 64) v = 0.0f;
        else              v = -sinpif(x) * (2.0f/512.0f);
        g_ib[idx] = __float2half_rn(v);
    }
    #pragma unroll
    for (int ly = 0; ly < 2; ly++) {
        if (idx < 16384) {
            int n = idx >> 7, k = idx & 127;
            g_wq[ly*16384 + idx] = __float2half_rn(Wq[ly*16384 + k*128 + n]);
            g_wo[ly*16384 + idx] = __float2half_rn(Wo[ly*16384 + k*128 + n]);
        }
        {
            int n = idx >> 7, k = idx & 127;
            g_w1[ly*65536 + idx] = __float2half_rn(W1[ly*65536 + k*512 + n]);
        }
        {
            int n = idx >> 9, k = idx & 511;
            g_w2[ly*65536 + idx] = __float2half_rn(W2[ly*65536 + k*128 + n]);
        }
    }
    {
        int t = idx >> 7, d = idx & 127;
        int i2 = d & ~1;
        float div = expf((float)i2 * (-9.210340371976184f / 128.0f));
        float a = (float)t * div;
        g_PE[idx] = (d & 1) ? cosf(a) : sinf(a);
    }
}

// ---------------- input transpose ----------------
__global__ void k_transpose(const float* __restrict__ x_enc,
                            const float* __restrict__ mark) {
    __shared__ float tile [32][33];
    __shared__ float tileM[32][33];
    int b = blockIdx.z;
    int d0 = blockIdx.y * 32, l0 = blockIdx.x * 32;
    int tx = threadIdx.x, ty = threadIdx.y;
    const float* xb = x_enc + b*65536;
    const float* mb = mark  + b*65536;
    #pragma unroll
    for (int i = ty; i < 32; i += 8) {
        tile [i][tx] = xb[(d0+i)*512 + l0 + tx];
        tileM[i][tx] = mb[(d0+i)*512 + l0 + tx];
    }
    __syncthreads();
    float* mo = g_MarkT + b*65536;
    #pragma unroll
    for (int i = ty; i < 32; i += 8) {
        int oi = b*LP_*128 + (l0+i+1)*128 + d0+tx;
        g_X[oi] = __float2half_rn(tile[tx][i]);
        mo[(l0+i)*128 + d0+tx] = tileM[tx][i];
    }
}
__global__ void k_edges(const float* __restrict__ x_enc) {
    int idx = blockIdx.x*256 + threadIdx.x;
    if (idx < B_*D_) {
        int b = idx >> 7, d = idx & 127;
        g_X[b*LP_*128 + d] = __float2half_rn(x_enc[b*65536 + d*512 + 511]);
        g_X[b*LP_*128 + 513*128 + d] = __float2half_rn(x_enc[b*65536 + d*512]);
    }
}

// ---------------- fp16 transpose (b,l,d) -> (b,d,l) ----------------
__global__ void k_tq() {
    __shared__ __half th[32][34];
    int b = blockIdx.z;
    int l0 = blockIdx.x * 32, d0 = blockIdx.y * 32;
    int tx = threadIdx.x, ty = threadIdx.y;
    #pragma unroll
    for (int i = ty; i < 32; i += 8)
        th[i][tx] = g_Q[b*65536 + (l0+i)*128 + d0 + tx];
    __syncthreads();
    #pragma unroll
    for (int i = ty; i < 32; i += 8)
        g_QT[b*65536 + (d0+i)*512 + l0 + tx] = th[tx][i];
}

// ---------------- fp16 HMMA GEMM, cp.async 3-stage, K-chunk 32 --------------
// BM=128: CTA 128x128, 8 warps of 32x64, 2 CTAs/SM.
// BM=64:  CTA  64x128, 8 warps of 32x32, 4 CTAs/SM.   (R7 path)
// A(row,k) = A[(row>>absh)*abstr + (row&mask)*arstr + k]
// EPI bits: 1=+bias[col], 2=+res, 4=gelu, 8=+PE, 16=skip fp32 C store
// WRB: also write fp16 result to Cf
template<int BM, int EPI, int WRB>
__global__ void __launch_bounds__(256, (BM == 128 ? 2 : 4)) k_tgemm(
    const __half* __restrict__ A, const __half* __restrict__ B,
    const float* __restrict__ bias, const float* __restrict__ res,
    float* __restrict__ C, __half* __restrict__ Cf,
    int K, int ldc, int absh, int abstr, int arstr)
{
    constexpr int NWM  = (BM == 128) ? 4 : 2;   // warp row groups
    constexpr int WN   = (BM == 128) ? 64 : 32; // warp n tile
    constexpr int NBF  = WN / 16;               // B frags per ks
    constexpr int NNI  = WN / 8;                // mma n-steps
    constexpr int ASL  = BM / 64;               // A load slots per thread
    constexpr int ABY  = BM * 64;               // A bytes per stage
    constexpr int STG  = ABY + 8192;            // stage stride

    extern __shared__ char sm[];
    const uint32_t sU = smem_u32(sm);
    const int tid = threadIdx.x, wid = tid >> 5, lane = tid & 31;
    const int rowBase = blockIdx.x * BM, colBase = blockIdx.y * 128;
    const int amask = (1 << absh) - 1;

    float acc[2][NNI][4];
    #pragma unroll
    for (int i = 0; i < 2; i++)
        #pragma unroll
        for (int j = 0; j < NNI; j++)
            #pragma unroll
            for (int q = 0; q < 4; q++) acc[i][j][q] = 0.f;

    const int nc = K >> 5;

    // per-thread load geometry: row = tid>>2 (+64 strides), chunk = tid&3
    const int lrow = tid >> 2, lch = tid & 3;
    long a_b[ASL];
    uint32_t a_swo[ASL];
    #pragma unroll
    for (int i = 0; i < ASL; i++) {
        int rg = rowBase + lrow + i*64;
        a_b[i] = (long)(rg >> absh)*abstr + (long)(rg & amask)*arstr + lch*8;
        a_swo[i] = sw32(lrow + i*64, lch);
    }
    long b_b[2];
    uint32_t b_swo[2];
    #pragma unroll
    for (int i = 0; i < 2; i++) {
        b_b[i] = (long)(colBase + lrow + i*64)*K + lch*8;
        b_swo[i] = sw32(lrow + i*64, lch);
    }

    auto load_chunk = [&](int stage, int k0) {
        uint32_t sb = sU + stage * STG;
        #pragma unroll
        for (int i = 0; i < ASL; i++) CP16(sb + a_swo[i], A + a_b[i] + k0);
        #pragma unroll
        for (int i = 0; i < 2; i++)   CP16(sb + ABY + b_swo[i], B + b_b[i] + k0);
    };

    load_chunk(0, 0);  CPCOMMIT();
    load_chunk(1, 32); CPCOMMIT();

    const int mrow = (wid % NWM) * 32;
    const int ncol = (wid / NWM) * WN;
    const int a_lr  = mrow + (lane & 15);
    const int a_lc  = lane >> 4;
    const int b_lr  = ncol + (lane & 7) + ((lane & 16) ? 8 : 0);
    const int b_lc  = (lane >> 3) & 1;
    int stage = 0;

    for (int c = 0; c < nc; c++) {
        CPWAIT1();
        __syncthreads();
        if (c + 2 < nc) {
            int ns = stage + 2; if (ns >= 3) ns -= 3;
            load_chunk(ns, (c + 2) * 32);
        }
        CPCOMMIT();

        uint32_t sb = sU + stage * STG;
        #pragma unroll
        for (int ks = 0; ks < 2; ks++) {
            uint32_t af[2][4], bf[NBF][4];
            #pragma unroll
            for (int g = 0; g < NBF; g++) {
                int r = b_lr + g*16, ci = ks*2 + b_lc;
                ldsm4(bf[g], sb + ABY + sw32(r, ci));
            }
            #pragma unroll
            for (int f = 0; f < 2; f++) {
                int r = a_lr + f*16, ci = ks*2 + a_lc;
                ldsm4(af[f], sb + sw32(r, ci));
            }
            #pragma unroll
            for (int mi = 0; mi < 2; mi++)
                #pragma unroll
                for (int ni = 0; ni < NNI; ni++)
                    mma16816(acc[mi][ni], af[mi], &bf[ni >> 1][(ni & 1) * 2]);
        }
        if (++stage >= 3) stage -= 3;
    }

    // ---- epilogue ----
    #pragma unroll
    for (int mi = 0; mi < 2; mi++) {
        #pragma unroll
        for (int half = 0; half < 2; half++) {
            int grow = rowBase + mrow + mi*16 + (lane >> 2) + half*8;
            #pragma unroll
            for (int ni = 0; ni < NNI; ni++) {
                int gcol = colBase + ncol + ni*8 + (lane & 3)*2;
                float v0 = acc[mi][ni][half*2 + 0];
                float v1 = acc[mi][ni][half*2 + 1];
                if (EPI & 1) { v0 += bias[gcol]; v1 += bias[gcol + 1]; }
                if (EPI & 8) {
                    int pbi = (grow & 511)*128 + (gcol & 127);
                    v0 += g_PE[pbi]; v1 += g_PE[pbi + 1];
                }
                long oidx = (long)grow * ldc + gcol;
                if (EPI & 2) {
                    float2 rr = *(const float2*)(res + oidx);
                    v0 += rr.x; v1 += rr.y;
                }
                if (EPI & 4) { v0 = geluf(v0); v1 = geluf(v1); }
                if (!(EPI & 16)) {
                    float2 o; o.x = v0; o.y = v1;
                    *(float2*)(C + oidx) = o;
                }
                if (WRB) {
                    *(uint32_t*)(Cf + oidx) =
                        pack2h(__float2half_rn(v0), __float2half_rn(v1));
                }
            }
        }
    }
}

// ---------------- complex mode mixing (fp32 in, fp16 out) ------------------
__global__ void k_mix(const float* __restrict__ fwr,
                      const float* __restrict__ fwi, int layer) {
    int b = blockIdx.x, hh = blockIdx.y;
    int m = threadIdx.x;
    const float* wr = fwr + (size_t)((layer*H_ + hh)*E_*E_) * 64;
    const float* wi = fwi + (size_t)((layer*H_ + hh)*E_*E_) * 64;
    float sr[E_], si[E_];
    #pragma unroll
    for (int o = 0; o < E_; o++) { sr[o] = 0.f; si[o] = 0.f; }
    const float* Fb = g_F + (b*128 + hh*16) * 128;
    #pragma unroll
    for (int e = 0; e < E_; e++) {
        float fre = Fb[e*128 + m];
        float fim = Fb[e*128 + 64 + m];
        #pragma unroll
        for (int o = 0; o < E_; o++) {
            float cr = wr[(e*E_ + o)*64 + m];
            float ci = wi[(e*E_ + o)*64 + m];
            sr[o] += fre*cr - fim*ci;
            si[o] += fre*ci + fim*cr;
        }
    }
    int base = (b*128 + hh*16) * 128;
    #pragma unroll
    for (int o = 0; o < E_; o++) {
        g_S[base + o*128 + m]      = __float2half_rn(sr[o]);
        g_S[base + o*128 + 64 + m] = __float2half_rn(si[o]);
    }
}

// ---------------- series_decomp: fp32 + fp16 outputs ------------------------
__global__ void k_movsub(const float* __restrict__ X, float* __restrict__ Out,
                         __half* __restrict__ Oh) {
    __shared__ float sh[88 * 128];
    int b = blockIdx.x, t0 = blockIdx.y * 64;
    int d = threadIdx.x;
    const float* Xb = X + b*65536;
    #pragma unroll 4
    for (int r = 0; r < 88; r++) {
        int t = t0 + r - 12;
        t = max(0, min(511, t));
        sh[r*128 + d] = Xb[t*128 + d];
    }
    float s = 0.f;
    #pragma unroll 4
    for (int r = 0; r < 88; r++) { s += sh[r*128 + d]; sh[r*128 + d] = s; }
    #pragma unroll 4
    for (int tt = 0; tt < 64; tt++) {
        int r = tt + 12;
        float hi = sh[(r+12)*128 + d];
        float lo = (r >= 13) ? sh[(r-13)*128 + d] : 0.f;
        float v = Xb[(t0+tt)*128 + d] - (hi - lo) * (1.0f/25.0f);
        int oi = b*65536 + (t0+tt)*128 + d;
        Out[oi] = v;
        Oh[oi] = __float2half_rn(v);
    }
}

// ---------------- LayerNorm ----------------
__global__ void k_ln(const float* __restrict__ X, const float* __restrict__ g,
                     const float* __restrict__ be, float* __restrict__ Out) {
    int row  = blockIdx.x*8 + (threadIdx.x >> 5);
    int lane = threadIdx.x & 31;
    const float* xr = X + (size_t)row * 128;
    float v[4];
    float s = 0.f;
    #pragma unroll
    for (int i = 0; i < 4; i++) { v[i] = xr[lane + i*32]; s += v[i]; }
    #pragma unroll
    for (int o = 16; o > 0; o >>= 1) s += __shfl_xor_sync(0xffffffffu, s, o);
    float mu = s * (1.0f/128.0f);
    float q = 0.f;
    #pragma unroll
    for (int i = 0; i < 4; i++) { float dl = v[i] - mu; q += dl*dl; }
    #pragma unroll
    for (int o = 16; o > 0; o >>= 1) q += __shfl_xor_sync(0xffffffffu, q, o);
    float rstd = rsqrtf(q * (1.0f/128.0f) + 1e-5f);
    float* orow = Out + (size_t)row * 128;
    #pragma unroll
    for (int i = 0; i < 4; i++) {
        int d = lane + i*32;
        orow[d] = (v[i] - mu) * rstd * g[d] + be[d];
    }
}

__global__ void k_zero(float* p, int n) {
    int i = blockIdx.x*256 + threadIdx.x;
    if (i < n) p[i] = 0.f;
}
__global__ void k_colmean(const float* __restrict__ HN) {
    int b = blockIdx.x, t0 = blockIdx.y * 64, d = threadIdx.x;
    const float* Xb = HN + b*65536;
    float s = 0.f;
    #pragma unroll 8
    for (int tt = 0; tt < 64; tt++) s += Xb[(t0+tt)*128 + d];
    atomicAdd(&g_CM[b*128 + d], s);
}
__global__ void k_final(const float* __restrict__ HN, const float* __restrict__ pw,
                        const float* __restrict__ pb, float* __restrict__ out) {
    int b = blockIdx.x, tid = threadIdx.x;
    const float* hb = HN + b*65536;
    const float* mb = g_MarkT + b*65536;
    float s = 0.f;
    for (int i = tid; i < 65536; i += 256) {
        float v = hb[i] - g_CM[b*128 + (i & 127)] * (1.0f/512.0f);
        s += geluf(v) * mb[i] * pw[i];
    }
    __shared__ float red[256];
    red[tid] = s; __syncthreads();
    #pragma unroll
    for (int o = 128; o > 0; o >>= 1) {
        if (tid < o) red[tid] += red[tid + o];
        __syncthreads();
    }
    if (tid == 0) out[b] = red[0] + pb[0];
}

// ---------------- host orchestration ----------------
#define SMB128 49152
#define SMB64  36864

extern "C" void kernel_launch(void* const* d_in, const int* in_sizes, int n_in,
                              void* d_out, int out_size) {
    const float* x_enc  = (const float*)d_in[0];
    const float* mark   = (const float*)d_in[1];
    const float* conv_w = (const float*)d_in[4];
    const float* Wq     = (const float*)d_in[5];
    const float* bq     = (const float*)d_in[6];
    const float* Wo     = (const float*)d_in[7];
    const float* bo     = (const float*)d_in[8];
    const float* fwr    = (const float*)d_in[9];
    const float* fwi    = (const float*)d_in[10];
    const float* W1     = (const float*)d_in[11];
    const float* W2     = (const float*)d_in[12];
    const float* ln_g   = (const float*)d_in[13];
    const float* ln_b   = (const float*)d_in[14];
    const float* pw     = (const float*)d_in[15];
    const float* pb     = (const float*)d_in[16];
    float* out = (float*)d_out;

    cudaFuncSetAttribute(k_tgemm<128,8,1>,  cudaFuncAttributeMaxDynamicSharedMemorySize, SMB128);
    cudaFuncSetAttribute(k_tgemm<128,17,1>, cudaFuncAttributeMaxDynamicSharedMemorySize, SMB128);
    cudaFuncSetAttribute(k_tgemm<64,0,0>,   cudaFuncAttributeMaxDynamicSharedMemorySize, SMB64);
    cudaFuncSetAttribute(k_tgemm<128,16,1>, cudaFuncAttributeMaxDynamicSharedMemorySize, SMB128);
    cudaFuncSetAttribute(k_tgemm<128,3,0>,  cudaFuncAttributeMaxDynamicSharedMemorySize, SMB128);
    cudaFuncSetAttribute(k_tgemm<128,20,1>, cudaFuncAttributeMaxDynamicSharedMemorySize, SMB128);
    cudaFuncSetAttribute(k_tgemm<128,2,0>,  cudaFuncAttributeMaxDynamicSharedMemorySize, SMB128);

    float *pH, *pT1, *pT2, *pF, *pCM;
    cudaGetSymbolAddress((void**)&pH,   g_H);
    cudaGetSymbolAddress((void**)&pT1,  g_T1);
    cudaGetSymbolAddress((void**)&pT2,  g_T2);
    cudaGetSymbolAddress((void**)&pF,   g_F);
    cudaGetSymbolAddress((void**)&pCM,  g_CM);
    __half *x16,*hx,*q16,*qt,*s16,*u16;
    cudaGetSymbolAddress((void**)&x16, g_X);
    cudaGetSymbolAddress((void**)&hx,  g_Hx);
    cudaGetSymbolAddress((void**)&q16, g_Q);
    cudaGetSymbolAddress((void**)&qt,  g_QT);
    cudaGetSymbolAddress((void**)&s16, g_S);
    cudaGetSymbolAddress((void**)&u16, g_U);
    __half *cw,*fb,*ib,*wq,*wo,*w1,*w2;
    cudaGetSymbolAddress((void**)&cw, g_cw);
    cudaGetSymbolAddress((void**)&fb, g_fb);
    cudaGetSymbolAddress((void**)&ib, g_ib);
    cudaGetSymbolAddress((void**)&wq, g_wq);
    cudaGetSymbolAddress((void**)&wo, g_wo);
    cudaGetSymbolAddress((void**)&w1, g_w1);
    cudaGetSymbolAddress((void**)&w2, g_w2);

    k_prep<<<256, 256>>>(conv_w, Wq, Wo, W1, W2);
    k_transpose<<<dim3(16,4,128), dim3(32,8)>>>(x_enc, mark);
    k_edges<<<64, 256>>>(x_enc);

    // TokenEmbedding conv (K=384) + PE -> fp32 H + fp16 H  (M=65536 -> 512 tiles)
    k_tgemm<128,8,1><<<dim3(512,1), 256, SMB128>>>(
        x16, cw, nullptr, nullptr, pH, hx, 384, 128, 9, LP_*128, 128);

    for (int l = 0; l < 2; l++) {
        // Q = H @ Wq + bq -> fp16
        k_tgemm<128,17,1><<<dim3(512,1), 256, SMB128>>>(
            hx, wq + l*16384, bq + l*128, nullptr, nullptr, q16,
            128, 128, 30, 0, 128);
        // transpose Q (b,l,d) -> (b,d,l)
        k_tq<<<dim3(16,4,128), dim3(32,8)>>>();
        // forward DFT -> fp32 F  (M=16384 -> 256 tiles @ BM=64)
        k_tgemm<64,0,0><<<dim3(256,1), 256, SMB64>>>(
            qt, fb, nullptr, nullptr, pF, nullptr, 512, 128, 30, 0, 512);
        // complex mode mixing -> fp16 S
        k_mix<<<dim3(128,8), 64>>>(fwr, fwi, l);
        // inverse DFT -> fp16 flat (== scrambled view(B,L,-1))  (128x4 tiles)
        k_tgemm<128,16,1><<<dim3(128,4), 256, SMB128>>>(
            s16, ib, nullptr, nullptr, nullptr, q16, 128, 512, 30, 0, 128);
        // out proj + bias + residual -> fp32 T2
        k_tgemm<128,3,0><<<dim3(512,1), 256, SMB128>>>(
            q16, wo + l*16384, bo + l*128, pH, pT2, nullptr,
            128, 128, 30, 0, 128);
        // decomp1 -> fp32 H + fp16 H
        k_movsub<<<dim3(128,8), 128>>>(pT2, pH, hx);
        // FFN up + gelu -> fp16 U  (512x4 tiles)
        k_tgemm<128,20,1><<<dim3(512,4), 256, SMB128>>>(
            hx, w1 + l*65536, nullptr, nullptr, nullptr, u16,
            128, 512, 30, 0, 128);
        // FFN down + residual -> fp32 T2
        k_tgemm<128,2,0><<<dim3(512,1), 256, SMB128>>>(
            u16, w2 + l*65536, nullptr, pH, pT2, nullptr,
            512, 128, 30, 0, 512);
        // decomp2 -> fp32 H + fp16 H
        k_movsub<<<dim3(128,8), 128>>>(pT2, pH, hx);
    }

    k_ln<<<8192, 256>>>(pH, ln_g, ln_b, pT1);
    k_zero<<<64, 256>>>(pCM, B_*D_);
    k_colmean<<<dim3(128,8), 128>>>(pT1);
    k_final<<<128, 256>>>(pT1, pw, pb, out);
}

// round 11
// speedup vs baseline: 1.2292x; 1.2178x over previous
#include <cuda_runtime.h>
#include <cuda_fp16.h>
#include <math.h>
#include <stdint.h>

#define B_    128
#define L_    512
#define D_    128
#define H_    8
#define E_    16
#define DFF_  512
#define LP_   514

// ---------------- fp32 scratch ----------------
__device__ float g_T2 [B_*L_*D_];
__device__ float g_F  [B_*D_*128];
__device__ float g_PE [512*128];
__device__ float g_CM [B_*D_];

// ---------------- fp16 scratch ----------------
__device__ __half g_MarkH[B_*L_*D_];
__device__ __half g_X [B_*LP_*D_];
__device__ __half g_Hx[B_*L_*D_];
__device__ __half g_Q [B_*L_*D_];
__device__ __half g_QT[B_*L_*D_];
__device__ __half g_S [B_*D_*128];
__device__ __half g_U [B_*L_*DFF_];
__device__ __half g_HN[B_*L_*D_];

// ---------------- fp16 weights, [N, K] row-major ----------------
__device__ __half g_cw[128*384];
__device__ __half g_fb[128*512];
__device__ __half g_ib[512*128];
__device__ __half g_wq[2*128*128];
__device__ __half g_wo[2*128*128];
__device__ __half g_w1[2*512*128];
__device__ __half g_w2[2*128*512];

__device__ __forceinline__ float geluf(float v) {
    return 0.5f * v * (1.0f + erff(v * 0.7071067811865476f));
}
__device__ __forceinline__ uint32_t pack2h(__half a, __half b) {
    return (uint32_t)__half_as_ushort(a) | ((uint32_t)__half_as_ushort(b) << 16);
}
__device__ __forceinline__ uint32_t smem_u32(const void* p) {
    uint32_t a;
    asm("{ .reg .u64 t; cvta.to.shared.u64 t, %1; cvt.u32.u64 %0, t; }" : "=r"(a) : "l"(p));
    return a;
}
__device__ __forceinline__ void ldsm4(uint32_t* r, uint32_t a) {
    asm volatile("ldmatrix.sync.aligned.m8n8.x4.shared.b16 {%0,%1,%2,%3}, [%4];"
        : "=r"(r[0]), "=r"(r[1]), "=r"(r[2]), "=r"(r[3]) : "r"(a));
}
__device__ __forceinline__ void mma16816(float* c, const uint32_t* a, const uint32_t* b) {
    asm volatile(
        "mma.sync.aligned.m16n8k16.row.col.f32.f16.f16.f32 "
        "{%0,%1,%2,%3}, {%4,%5,%6,%7}, {%8,%9}, {%0,%1,%2,%3};"
        : "+f"(c[0]), "+f"(c[1]), "+f"(c[2]), "+f"(c[3])
        : "r"(a[0]), "r"(a[1]), "r"(a[2]), "r"(a[3]), "r"(b[0]), "r"(b[1]));
}
#define CP16(d, s)   asm volatile("cp.async.cg.shared.global [%0], [%1], 16;" :: "r"(d), "l"(s))
#define CPCOMMIT()   asm volatile("cp.async.commit_group;" ::: "memory")
#define CPWAIT1()    asm volatile("cp.async.wait_group 1;" ::: "memory")

// tile row = 32 halves = 64B = 4x16B chunks; swizzle chunk ^= (row>>1)&3
__device__ __forceinline__ uint32_t sw32(int row, int ch) {
    return (uint32_t)(row * 64) + (uint32_t)(((ch ^ ((row >> 1) & 3)) << 4));
}

// ---------------- prep: weights -> fp16 [N,K]; PE table --------------------
__global__ void k_prep(const float* __restrict__ conv_w, const float* __restrict__ Wq,
                       const float* __restrict__ Wo, const float* __restrict__ W1,
                       const float* __restrict__ W2) {
    int idx = blockIdx.x * 256 + threadIdx.x;   // 65536 total
    if (idx < 49152) {
        int n = idx / 384, k = idx - n*384;
        int s = k >> 7, din = k & 127;
        g_cw[idx] = __float2half_rn(conv_w[n*384 + din*3 + s]);
    }
    {   // forward DFT basis: N=128 (coeff), K=512 (t)
        int n = idx >> 9, t = idx & 511, m = n & 63;
        float x = (float)(m * t) * (1.0f/256.0f);
        float v = (n < 64) ? cospif(x) : -sinpif(x);
        g_fb[idx] = __float2half_rn(v);
    }
    {   // inverse DFT basis: N=512 (t), K=128 (coeff)
        int t = idx >> 7, n = idx & 127, m = n & 63;
        float x = (float)(m * t) * (1.0f/256.0f);
        float v;
        if (n == 0)       v = 1.0f/512.0f;
        else if (n < 64)  v = cospif(x) * (2.0f/512.0f);
        else if (n == 64) v = 0.0f;
        else              v = -sinpif(x) * (2.0f/512.0f);
        g_ib[idx] = __float2half_rn(v);
    }
    #pragma unroll
    for (int ly = 0; ly < 2; ly++) {
        if (idx < 16384) {
            int n = idx >> 7, k = idx & 127;
            g_wq[ly*16384 + idx] = __float2half_rn(Wq[ly*16384 + k*128 + n]);
            g_wo[ly*16384 + idx] = __float2half_rn(Wo[ly*16384 + k*128 + n]);
        }
        {
            int n = idx >> 7, k = idx & 127;
            g_w1[ly*65536 + idx] = __float2half_rn(W1[ly*65536 + k*512 + n]);
        }
        {
            int n = idx >> 9, k = idx & 511;
            g_w2[ly*65536 + idx] = __float2half_rn(W2[ly*65536 + k*128 + n]);
        }
    }
    {
        int t = idx >> 7, d = idx & 127;
        int i2 = d & ~1;
        float div = expf((float)i2 * (-9.210340371976184f / 128.0f));
        float a = (float)t * div;
        g_PE[idx] = (d & 1) ? cosf(a) : sinf(a);
    }
}

// ---------------- input transpose (mark -> fp16) ----------------
__global__ void k_transpose(const float* __restrict__ x_enc,
                            const float* __restrict__ mark) {
    __shared__ float tile [32][33];
    __shared__ float tileM[32][33];
    int b = blockIdx.z;
    int d0 = blockIdx.y * 32, l0 = blockIdx.x * 32;
    int tx = threadIdx.x, ty = threadIdx.y;
    const float* xb = x_enc + b*65536;
    const float* mb = mark  + b*65536;
    #pragma unroll
    for (int i = ty; i < 32; i += 8) {
        tile [i][tx] = xb[(d0+i)*512 + l0 + tx];
        tileM[i][tx] = mb[(d0+i)*512 + l0 + tx];
    }
    __syncthreads();
    #pragma unroll
    for (int i = ty; i < 32; i += 8) {
        int oi = b*LP_*128 + (l0+i+1)*128 + d0+tx;
        g_X[oi] = __float2half_rn(tile[tx][i]);
        g_MarkH[b*65536 + (l0+i)*128 + d0+tx] = __float2half_rn(tileM[tx][i]);
    }
}
__global__ void k_edges(const float* __restrict__ x_enc) {
    int idx = blockIdx.x*256 + threadIdx.x;
    if (idx < B_*D_) {
        int b = idx >> 7, d = idx & 127;
        g_X[b*LP_*128 + d] = __float2half_rn(x_enc[b*65536 + d*512 + 511]);
        g_X[b*LP_*128 + 513*128 + d] = __float2half_rn(x_enc[b*65536 + d*512]);
    }
}

// ---------------- fp16 transpose (b,l,d) -> (b,d,l) ----------------
__global__ void k_tq() {
    __shared__ __half th[32][34];
    int b = blockIdx.z;
    int l0 = blockIdx.x * 32, d0 = blockIdx.y * 32;
    int tx = threadIdx.x, ty = threadIdx.y;
    #pragma unroll
    for (int i = ty; i < 32; i += 8)
        th[i][tx] = g_Q[b*65536 + (l0+i)*128 + d0 + tx];
    __syncthreads();
    #pragma unroll
    for (int i = ty; i < 32; i += 8)
        g_QT[b*65536 + (d0+i)*512 + l0 + tx] = th[tx][i];
}

// ---------------- fp16 HMMA GEMM, cp.async 3-stage, K-chunk 32 --------------
// CTA tile 64(M) x 128(N); 8 warps of 32x32; 4 CTAs/SM.   (R7 config)
// A(row,k) = A[(row>>absh)*abstr + (row&mask)*arstr + k]
// EPI bits: 1=+bias[col], 2=+res(fp16), 4=gelu, 8=+PE, 16=skip fp32 C store
// WRB: also write fp16 result to Cf
// SMEM/stage (12KB): A@0(4K) B@4K(8K); 3 stages = 36KB.
template<int EPI, int WRB>
__global__ void __launch_bounds__(256, 4) k_tgemm(
    const __half* __restrict__ A, const __half* __restrict__ B,
    const float* __restrict__ bias, const __half* __restrict__ res,
    float* __restrict__ C, __half* __restrict__ Cf,
    int K, int ldc, int absh, int abstr, int arstr)
{
    extern __shared__ char sm[];
    const uint32_t sU = smem_u32(sm);
    const int tid = threadIdx.x, wid = tid >> 5, lane = tid & 31;
    const int rowBase = blockIdx.x * 64, colBase = blockIdx.y * 128;
    const int amask = (1 << absh) - 1;

    float acc[2][4][4];
    #pragma unroll
    for (int i = 0; i < 2; i++)
        #pragma unroll
        for (int j = 0; j < 4; j++)
            #pragma unroll
            for (int q = 0; q < 4; q++) acc[i][j][q] = 0.f;

    const int nc = K >> 5;

    // per-thread load geometry
    const int a_row = tid >> 2, a_ch = tid & 3;
    const uint32_t a_sw = sw32(a_row, a_ch);
    int a_rg = rowBase + a_row;
    const long a_base = (long)(a_rg >> absh)*abstr + (long)(a_rg & amask)*arstr + a_ch*8;
    const int b_row0 = tid >> 2, b_row1 = 64 + (tid >> 2);
    const uint32_t b_sw0 = sw32(b_row0, a_ch), b_sw1 = sw32(b_row1, a_ch);
    const long b_base0 = (long)(colBase + b_row0)*K + a_ch*8;
    const long b_base1 = (long)(colBase + b_row1)*K + a_ch*8;

    auto load_chunk = [&](int stage, int k0) {
        uint32_t sb = sU + stage * 12288;
        CP16(sb +        a_sw, A + a_base + k0);
        CP16(sb + 4096 + b_sw0, B + b_base0 + k0);
        CP16(sb + 4096 + b_sw1, B + b_base1 + k0);
    };

    load_chunk(0, 0);  CPCOMMIT();
    load_chunk(1, 32); CPCOMMIT();

    const int mrow = (wid & 1) * 32;
    const int ncol = (wid >> 1) * 32;
    const int a_lr  = mrow + (lane & 15);
    const int a_lc  = lane >> 4;
    const int b_lr  = ncol + (lane & 7) + ((lane & 16) ? 8 : 0);
    const int b_lc  = (lane >> 3) & 1;
    int stage = 0;

    for (int c = 0; c < nc; c++) {
        CPWAIT1();
        __syncthreads();
        if (c + 2 < nc) {
            int ns = stage + 2; if (ns >= 3) ns -= 3;
            load_chunk(ns, (c + 2) * 32);
        }
        CPCOMMIT();

        uint32_t sb = sU + stage * 12288;
        #pragma unroll
        for (int ks = 0; ks < 2; ks++) {
            uint32_t af[2][4], bf[2][4];
            #pragma unroll
            for (int g = 0; g < 2; g++) {
                int r = b_lr + g*16, ci = ks*2 + b_lc;
                ldsm4(bf[g], sb + 4096 + sw32(r, ci));
            }
            #pragma unroll
            for (int f = 0; f < 2; f++) {
                int r = a_lr + f*16, ci = ks*2 + a_lc;
                ldsm4(af[f], sb + sw32(r, ci));
            }
            #pragma unroll
            for (int mi = 0; mi < 2; mi++)
                #pragma unroll
                for (int ni = 0; ni < 4; ni++)
                    mma16816(acc[mi][ni], af[mi], &bf[ni >> 1][(ni & 1) * 2]);
        }
        if (++stage >= 3) stage -= 3;
    }

    // ---- epilogue ----
    #pragma unroll
    for (int mi = 0; mi < 2; mi++) {
        #pragma unroll
        for (int half = 0; half < 2; half++) {
            int grow = rowBase + mrow + mi*16 + (lane >> 2) + half*8;
            #pragma unroll
            for (int ni = 0; ni < 4; ni++) {
                int gcol = colBase + ncol + ni*8 + (lane & 3)*2;
                float v0 = acc[mi][ni][half*2 + 0];
                float v1 = acc[mi][ni][half*2 + 1];
                if (EPI & 1) { v0 += bias[gcol]; v1 += bias[gcol + 1]; }
                if (EPI & 8) {
                    int pbi = (grow & 511)*128 + (gcol & 127);
                    v0 += g_PE[pbi]; v1 += g_PE[pbi + 1];
                }
                long oidx = (long)grow * ldc + gcol;
                if (EPI & 2) {
                    __half2 rr = *(const __half2*)(res + oidx);
                    v0 += __low2float(rr); v1 += __high2float(rr);
                }
                if (EPI & 4) { v0 = geluf(v0); v1 = geluf(v1); }
                if (!(EPI & 16)) {
                    float2 o; o.x = v0; o.y = v1;
                    *(float2*)(C + oidx) = o;
                }
                if (WRB) {
                    *(uint32_t*)(Cf + oidx) =
                        pack2h(__float2half_rn(v0), __float2half_rn(v1));
                }
            }
        }
    }
}

// ---------------- complex mode mixing (fp32 in, fp16 out) ------------------
__global__ void k_mix(const float* __restrict__ fwr,
                      const float* __restrict__ fwi, int layer) {
    int b = blockIdx.x, hh = blockIdx.y;
    int m = threadIdx.x;
    const float* wr = fwr + (size_t)((layer*H_ + hh)*E_*E_) * 64;
    const float* wi = fwi + (size_t)((layer*H_ + hh)*E_*E_) * 64;
    float sr[E_], si[E_];
    #pragma unroll
    for (int o = 0; o < E_; o++) { sr[o] = 0.f; si[o] = 0.f; }
    const float* Fb = g_F + (b*128 + hh*16) * 128;
    #pragma unroll
    for (int e = 0; e < E_; e++) {
        float fre = Fb[e*128 + m];
        float fim = Fb[e*128 + 64 + m];
        #pragma unroll
        for (int o = 0; o < E_; o++) {
            float cr = wr[(e*E_ + o)*64 + m];
            float ci = wi[(e*E_ + o)*64 + m];
            sr[o] += fre*cr - fim*ci;
            si[o] += fre*ci + fim*cr;
        }
    }
    int base = (b*128 + hh*16) * 128;
    #pragma unroll
    for (int o = 0; o < E_; o++) {
        g_S[base + o*128 + m]      = __float2half_rn(sr[o]);
        g_S[base + o*128 + 64 + m] = __float2half_rn(si[o]);
    }
}

// ---------------- series_decomp: fp32 in, fp16 out --------------------------
__global__ void k_movsub(const float* __restrict__ X, __half* __restrict__ Oh) {
    __shared__ float sh[88 * 128];
    int b = blockIdx.x, t0 = blockIdx.y * 64;
    int d = threadIdx.x;
    const float* Xb = X + b*65536;
    #pragma unroll 4
    for (int r = 0; r < 88; r++) {
        int t = t0 + r - 12;
        t = max(0, min(511, t));
        sh[r*128 + d] = Xb[t*128 + d];
    }
    float s = 0.f;
    #pragma unroll 4
    for (int r = 0; r < 88; r++) { s += sh[r*128 + d]; sh[r*128 + d] = s; }
    #pragma unroll 4
    for (int tt = 0; tt < 64; tt++) {
        int r = tt + 12;
        float hi = sh[(r+12)*128 + d];
        float lo = (r >= 13) ? sh[(r-13)*128 + d] : 0.f;
        float v = Xb[(t0+tt)*128 + d] - (hi - lo) * (1.0f/25.0f);
        Oh[b*65536 + (t0+tt)*128 + d] = __float2half_rn(v);
    }
}

// ---------------- LayerNorm (fp16 in/out) + fused column-sum ----------------
__global__ void k_ln(const __half* __restrict__ X, const float* __restrict__ g,
                     const float* __restrict__ be, __half* __restrict__ Out) {
    __shared__ float cm[128];
    int row  = blockIdx.x*8 + (threadIdx.x >> 5);     // 8 rows/block, same b
    int lane = threadIdx.x & 31;
    if (threadIdx.x < 128) cm[threadIdx.x] = 0.f;
    __syncthreads();
    const __half* xr = X + (size_t)row * 128;
    float v[4];
    float s = 0.f;
    #pragma unroll
    for (int i = 0; i < 4; i++) { v[i] = __half2float(xr[lane + i*32]); s += v[i]; }
    #pragma unroll
    for (int o = 16; o > 0; o >>= 1) s += __shfl_xor_sync(0xffffffffu, s, o);
    float mu = s * (1.0f/128.0f);
    float q = 0.f;
    #pragma unroll
    for (int i = 0; i < 4; i++) { float dl = v[i] - mu; q += dl*dl; }
    #pragma unroll
    for (int o = 16; o > 0; o >>= 1) q += __shfl_xor_sync(0xffffffffu, q, o);
    float rstd = rsqrtf(q * (1.0f/128.0f) + 1e-5f);
    __half* orow = Out + (size_t)row * 128;
    #pragma unroll
    for (int i = 0; i < 4; i++) {
        int d = lane + i*32;
        float o = (v[i] - mu) * rstd * g[d] + be[d];
        orow[d] = __float2half_rn(o);
        atomicAdd(&cm[d], o);
    }
    __syncthreads();
    if (threadIdx.x < 128) {
        int b = row >> 9;
        atomicAdd(&g_CM[b*128 + threadIdx.x], cm[threadIdx.x]);
    }
}

// ---------------- init: zero CM, out[b] = pb ----------------
__global__ void k_init(float* out, const float* __restrict__ pb) {
    int i = blockIdx.x*256 + threadIdx.x;
    if (i < B_) out[i] = pb[0];
    if (i < B_*D_) g_CM[i] = 0.f;
}

// ---------------- final: gelu(hn - colmean) * mark . pw --------------------
__global__ void k_final(const __half* __restrict__ HN, const float* __restrict__ pw,
                        float* __restrict__ out) {
    int b = blockIdx.x, tid = threadIdx.x;
    int loc0 = blockIdx.y*8192;                  // offset within one batch image
    int base = b*65536 + loc0;
    float s = 0.f;
    for (int i = tid; i < 8192; i += 256) {
        int gi = base + i;
        float v = __half2float(HN[gi]) - g_CM[b*128 + (gi & 127)] * (1.0f/512.0f);
        s += geluf(v) * __half2float(g_MarkH[gi]) * pw[loc0 + i];
    }
    __shared__ float red[256];
    red[tid] = s; __syncthreads();
    #pragma unroll
    for (int o = 128; o > 0; o >>= 1) {
        if (tid < o) red[tid] += red[tid + o];
        __syncthreads();
    }
    if (tid == 0) atomicAdd(&out[b], red[0]);
}

// ---------------- host orchestration ----------------
#define SMB 36864

extern "C" void kernel_launch(void* const* d_in, const int* in_sizes, int n_in,
                              void* d_out, int out_size) {
    const float* x_enc  = (const float*)d_in[0];
    const float* mark   = (const float*)d_in[1];
    const float* conv_w = (const float*)d_in[4];
    const float* Wq     = (const float*)d_in[5];
    const float* bq     = (const float*)d_in[6];
    const float* Wo     = (const float*)d_in[7];
    const float* bo     = (const float*)d_in[8];
    const float* fwr    = (const float*)d_in[9];
    const float* fwi    = (const float*)d_in[10];
    const float* W1     = (const float*)d_in[11];
    const float* W2     = (const float*)d_in[12];
    const float* ln_g   = (const float*)d_in[13];
    const float* ln_b   = (const float*)d_in[14];
    const float* pw     = (const float*)d_in[15];
    const float* pb     = (const float*)d_in[16];
    float* out = (float*)d_out;

    cudaFuncSetAttribute(k_tgemm<24,1>, cudaFuncAttributeMaxDynamicSharedMemorySize, SMB);
    cudaFuncSetAttribute(k_tgemm<17,1>, cudaFuncAttributeMaxDynamicSharedMemorySize, SMB);
    cudaFuncSetAttribute(k_tgemm<0,0>,  cudaFuncAttributeMaxDynamicSharedMemorySize, SMB);
    cudaFuncSetAttribute(k_tgemm<16,1>, cudaFuncAttributeMaxDynamicSharedMemorySize, SMB);
    cudaFuncSetAttribute(k_tgemm<3,0>,  cudaFuncAttributeMaxDynamicSharedMemorySize, SMB);
    cudaFuncSetAttribute(k_tgemm<20,1>, cudaFuncAttributeMaxDynamicSharedMemorySize, SMB);
    cudaFuncSetAttribute(k_tgemm<2,0>,  cudaFuncAttributeMaxDynamicSharedMemorySize, SMB);

    float *pT2, *pF;
    cudaGetSymbolAddress((void**)&pT2,  g_T2);
    cudaGetSymbolAddress((void**)&pF,   g_F);
    __half *x16,*hx,*q16,*qt,*s16,*u16,*hn;
    cudaGetSymbolAddress((void**)&x16, g_X);
    cudaGetSymbolAddress((void**)&hx,  g_Hx);
    cudaGetSymbolAddress((void**)&q16, g_Q);
    cudaGetSymbolAddress((void**)&qt,  g_QT);
    cudaGetSymbolAddress((void**)&s16, g_S);
    cudaGetSymbolAddress((void**)&u16, g_U);
    cudaGetSymbolAddress((void**)&hn,  g_HN);
    __half *cw,*fb,*ib,*wq,*wo,*w1,*w2;
    cudaGetSymbolAddress((void**)&cw, g_cw);
    cudaGetSymbolAddress((void**)&fb, g_fb);
    cudaGetSymbolAddress((void**)&ib, g_ib);
    cudaGetSymbolAddress((void**)&wq, g_wq);
    cudaGetSymbolAddress((void**)&wo, g_wo);
    cudaGetSymbolAddress((void**)&w1, g_w1);
    cudaGetSymbolAddress((void**)&w2, g_w2);

    k_prep<<<256, 256>>>(conv_w, Wq, Wo, W1, W2);
    k_transpose<<<dim3(16,4,128), dim3(32,8)>>>(x_enc, mark);
    k_edges<<<64, 256>>>(x_enc);

    // TokenEmbedding conv (K=384) + PE -> fp16 H only
    k_tgemm<24,1><<<dim3(1024,1), 256, SMB>>>(
        x16, cw, nullptr, nullptr, nullptr, hx, 384, 128, 9, LP_*128, 128);

    for (int l = 0; l < 2; l++) {
        // Q = H @ Wq + bq -> fp16
        k_tgemm<17,1><<<dim3(1024,1), 256, SMB>>>(
            hx, wq + l*16384, bq + l*128, nullptr, nullptr, q16,
            128, 128, 30, 0, 128);
        // transpose Q (b,l,d) -> (b,d,l)
        k_tq<<<dim3(16,4,128), dim3(32,8)>>>();
        // forward DFT -> fp32 F
        k_tgemm<0,0><<<dim3(256,1), 256, SMB>>>(
            qt, fb, nullptr, nullptr, pF, nullptr, 512, 128, 30, 0, 512);
        // complex mode mixing -> fp16 S
        k_mix<<<dim3(128,8), 64>>>(fwr, fwi, l);
        // inverse DFT -> fp16 flat (== scrambled view(B,L,-1))
        k_tgemm<16,1><<<dim3(256,4), 256, SMB>>>(
            s16, ib, nullptr, nullptr, nullptr, q16, 128, 512, 30, 0, 128);
        // out proj + bias + residual(fp16 H) -> fp32 T2
        k_tgemm<3,0><<<dim3(1024,1), 256, SMB>>>(
            q16, wo + l*16384, bo + l*128, hx, pT2, nullptr,
            128, 128, 30, 0, 128);
        // decomp1 -> fp16 H
        k_movsub<<<dim3(128,8), 128>>>(pT2, hx);
        // FFN up + gelu -> fp16 U
        k_tgemm<20,1><<<dim3(1024,4), 256, SMB>>>(
            hx, w1 + l*65536, nullptr, nullptr, nullptr, u16,
            128, 512, 30, 0, 128);
        // FFN down + residual(fp16 H) -> fp32 T2
        k_tgemm<2,0><<<dim3(1024,1), 256, SMB>>>(
            u16, w2 + l*65536, nullptr, hx, pT2, nullptr,
            512, 128, 30, 0, 512);
        // decomp2 -> fp16 H
        k_movsub<<<dim3(128,8), 128>>>(pT2, hx);
    }

    k_init<<<64, 256>>>(out, pb);
    k_ln<<<8192, 256>>>(hx, ln_g, ln_b, hn);
    k_final<<<dim3(128,8), 256>>>(hn, pw, out);
}

// round 12
// speedup vs baseline: 1.2708x; 1.0338x over previous
#include <cuda_runtime.h>
#include <cuda_fp16.h>
#include <math.h>
#include <stdint.h>

#define B_    128
#define L_    512
#define D_    128
#define H_    8
#define E_    16
#define DFF_  512
#define LP_   514

// ---------------- fp32 scratch ----------------
__device__ float g_T2 [B_*L_*D_];
__device__ float g_F  [B_*D_*128];
__device__ float g_PE [512*128];
__device__ float g_CM [B_*D_];

// ---------------- fp16 scratch ----------------
__device__ __half g_MarkH[B_*L_*D_];
__device__ __half g_X [B_*LP_*D_];
__device__ __half g_Hx[B_*L_*D_];
__device__ __half g_Q [B_*L_*D_];
__device__ __half g_QT[B_*L_*D_];
__device__ __half g_S [B_*D_*128];
__device__ __half g_U [B_*L_*DFF_];
__device__ __half g_HN[B_*L_*D_];

// ---------------- fp16 weights, [N, K] row-major ----------------
__device__ __half g_cw[128*384];
__device__ __half g_fb[128*512];
__device__ __half g_ib[512*128];
__device__ __half g_wq[2*128*128];
__device__ __half g_wo[2*128*128];
__device__ __half g_w1[2*512*128];
__device__ __half g_w2[2*128*512];

__device__ __forceinline__ float geluf(float v) {
    return 0.5f * v * (1.0f + erff(v * 0.7071067811865476f));
}
__device__ __forceinline__ uint32_t pack2h(__half a, __half b) {
    return (uint32_t)__half_as_ushort(a) | ((uint32_t)__half_as_ushort(b) << 16);
}
__device__ __forceinline__ uint32_t smem_u32(const void* p) {
    uint32_t a;
    asm("{ .reg .u64 t; cvta.to.shared.u64 t, %1; cvt.u32.u64 %0, t; }" : "=r"(a) : "l"(p));
    return a;
}
__device__ __forceinline__ void ldsm4(uint32_t* r, uint32_t a) {
    asm volatile("ldmatrix.sync.aligned.m8n8.x4.shared.b16 {%0,%1,%2,%3}, [%4];"
        : "=r"(r[0]), "=r"(r[1]), "=r"(r[2]), "=r"(r[3]) : "r"(a));
}
__device__ __forceinline__ void mma16816(float* c, const uint32_t* a, const uint32_t* b) {
    asm volatile(
        "mma.sync.aligned.m16n8k16.row.col.f32.f16.f16.f32 "
        "{%0,%1,%2,%3}, {%4,%5,%6,%7}, {%8,%9}, {%0,%1,%2,%3};"
        : "+f"(c[0]), "+f"(c[1]), "+f"(c[2]), "+f"(c[3])
        : "r"(a[0]), "r"(a[1]), "r"(a[2]), "r"(a[3]), "r"(b[0]), "r"(b[1]));
}
#define CP16(d, s)   asm volatile("cp.async.cg.shared.global [%0], [%1], 16;" :: "r"(d), "l"(s))
#define CPCOMMIT()   asm volatile("cp.async.commit_group;" ::: "memory")
#define CPWAIT2()    asm volatile("cp.async.wait_group 2;" ::: "memory")

// tile row = 32 halves = 64B = 4x16B chunks; swizzle chunk ^= (row>>1)&3
__device__ __forceinline__ uint32_t sw32(int row, int ch) {
    return (uint32_t)(row * 64) + (uint32_t)(((ch ^ ((row >> 1) & 3)) << 4));
}

// ---------------- prep: weights -> fp16 [N,K]; PE; zero CM; out=pb ---------
__global__ void k_prep(const float* __restrict__ conv_w, const float* __restrict__ Wq,
                       const float* __restrict__ Wo, const float* __restrict__ W1,
                       const float* __restrict__ W2, const float* __restrict__ pb,
                       float* __restrict__ out) {
    int idx = blockIdx.x * 256 + threadIdx.x;   // 65536 total
    if (idx < 49152) {
        int n = idx / 384, k = idx - n*384;
        int s = k >> 7, din = k & 127;
        g_cw[idx] = __float2half_rn(conv_w[n*384 + din*3 + s]);
    }
    if (idx < B_*D_) g_CM[idx] = 0.f;
    if (idx < B_)    out[idx] = pb[0];
    {   // forward DFT basis: N=128 (coeff), K=512 (t)
        int n = idx >> 9, t = idx & 511, m = n & 63;
        float x = (float)(m * t) * (1.0f/256.0f);
        float v = (n < 64) ? cospif(x) : -sinpif(x);
        g_fb[idx] = __float2half_rn(v);
    }
    {   // inverse DFT basis: N=512 (t), K=128 (coeff)
        int t = idx >> 7, n = idx & 127, m = n & 63;
        float x = (float)(m * t) * (1.0f/256.0f);
        float v;
        if (n == 0)       v = 1.0f/512.0f;
        else if (n < 64)  v = cospif(x) * (2.0f/512.0f);
        else if (n == 64) v = 0.0f;
        else              v = -sinpif(x) * (2.0f/512.0f);
        g_ib[idx] = __float2half_rn(v);
    }
    #pragma unroll
    for (int ly = 0; ly < 2; ly++) {
        if (idx < 16384) {
            int n = idx >> 7, k = idx & 127;
            g_wq[ly*16384 + idx] = __float2half_rn(Wq[ly*16384 + k*128 + n]);
            g_wo[ly*16384 + idx] = __float2half_rn(Wo[ly*16384 + k*128 + n]);
        }
        {
            int n = idx >> 7, k = idx & 127;
            g_w1[ly*65536 + idx] = __float2half_rn(W1[ly*65536 + k*512 + n]);
        }
        {
            int n = idx >> 9, k = idx & 511;
            g_w2[ly*65536 + idx] = __float2half_rn(W2[ly*65536 + k*128 + n]);
        }
    }
    {
        int t = idx >> 7, d = idx & 127;
        int i2 = d & ~1;
        float div = expf((float)i2 * (-9.210340371976184f / 128.0f));
        float a = (float)t * div;
        g_PE[idx] = (d & 1) ? cosf(a) : sinf(a);
    }
}

// ---------------- input transpose + circular edges (fused) -----------------
__global__ void k_transpose(const float* __restrict__ x_enc,
                            const float* __restrict__ mark) {
    __shared__ float tile [32][33];
    __shared__ float tileM[32][33];
    int b = blockIdx.z;
    int d0 = blockIdx.y * 32, l0 = blockIdx.x * 32;
    int tx = threadIdx.x, ty = threadIdx.y;
    const float* xb = x_enc + b*65536;
    const float* mb = mark  + b*65536;
    #pragma unroll
    for (int i = ty; i < 32; i += 8) {
        tile [i][tx] = xb[(d0+i)*512 + l0 + tx];
        tileM[i][tx] = mb[(d0+i)*512 + l0 + tx];
    }
    __syncthreads();
    #pragma unroll
    for (int i = ty; i < 32; i += 8) {
        int oi = b*LP_*128 + (l0+i+1)*128 + d0+tx;
        g_X[oi] = __float2half_rn(tile[tx][i]);
        g_MarkH[b*65536 + (l0+i)*128 + d0+tx] = __float2half_rn(tileM[tx][i]);
    }
    if (ty == 0) {
        if (blockIdx.x == 0)     // row 513 = x[:, :, 0]
            g_X[b*LP_*128 + 513*128 + d0+tx] = __float2half_rn(tile[tx][0]);
        if (blockIdx.x == 15)    // row 0 = x[:, :, 511]
            g_X[b*LP_*128 + d0+tx] = __float2half_rn(tile[tx][31]);
    }
}

// ---------------- fp16 HMMA GEMM, cp.async 4-stage, K-chunk 32 --------------
// CTA tile 64(M) x 128(N); 8 warps of 32x32; 4 CTAs/SM.
// A(row,k) = A[(row>>absh)*abstr + (row&mask)*arstr + k]
// EPI bits: 1=+bias[col], 2=+res(fp16), 4=gelu, 8=+PE, 16=skip fp32 C store
// WRB: write fp16 result to Cf (flat).  WRT: write fp16 transposed to g_QT.
// SMEM/stage (12KB): A@0(4K) B@4K(8K); 4 stages = 48KB.
template<int EPI, int WRB, int WRT>
__global__ void __launch_bounds__(256, 4) k_tgemm(
    const __half* __restrict__ A, const __half* __restrict__ B,
    const float* __restrict__ bias, const __half* __restrict__ res,
    float* __restrict__ C, __half* __restrict__ Cf,
    int K, int ldc, int absh, int abstr, int arstr)
{
    extern __shared__ char sm[];
    const uint32_t sU = smem_u32(sm);
    const int tid = threadIdx.x, wid = tid >> 5, lane = tid & 31;
    const int rowBase = blockIdx.x * 64, colBase = blockIdx.y * 128;
    const int amask = (1 << absh) - 1;

    float acc[2][4][4];
    #pragma unroll
    for (int i = 0; i < 2; i++)
        #pragma unroll
        for (int j = 0; j < 4; j++)
            #pragma unroll
            for (int q = 0; q < 4; q++) acc[i][j][q] = 0.f;

    const int nc = K >> 5;

    // per-thread load geometry
    const int a_row = tid >> 2, a_ch = tid & 3;
    const uint32_t a_sw = sw32(a_row, a_ch);
    int a_rg = rowBase + a_row;
    const long a_base = (long)(a_rg >> absh)*abstr + (long)(a_rg & amask)*arstr + a_ch*8;
    const int b_row0 = tid >> 2, b_row1 = 64 + (tid >> 2);
    const uint32_t b_sw0 = sw32(b_row0, a_ch), b_sw1 = sw32(b_row1, a_ch);
    const long b_base0 = (long)(colBase + b_row0)*K + a_ch*8;
    const long b_base1 = (long)(colBase + b_row1)*K + a_ch*8;

    auto load_chunk = [&](int stage, int k0) {
        uint32_t sb = sU + stage * 12288;
        CP16(sb +        a_sw, A + a_base + k0);
        CP16(sb + 4096 + b_sw0, B + b_base0 + k0);
        CP16(sb + 4096 + b_sw1, B + b_base1 + k0);
    };

    load_chunk(0, 0);  CPCOMMIT();
    load_chunk(1, 32); CPCOMMIT();
    load_chunk(2, 64); CPCOMMIT();

    const int mrow = (wid & 1) * 32;
    const int ncol = (wid >> 1) * 32;
    const int a_lr  = mrow + (lane & 15);
    const int a_lc  = lane >> 4;
    const int b_lr  = ncol + (lane & 7) + ((lane & 16) ? 8 : 0);
    const int b_lc  = (lane >> 3) & 1;
    int stage = 0;

    for (int c = 0; c < nc; c++) {
        CPWAIT2();
        __syncthreads();
        if (c + 3 < nc) load_chunk((stage + 3) & 3, (c + 3) * 32);
        CPCOMMIT();

        uint32_t sb = sU + stage * 12288;
        #pragma unroll
        for (int ks = 0; ks < 2; ks++) {
            uint32_t af[2][4], bf[2][4];
            #pragma unroll
            for (int g = 0; g < 2; g++) {
                int r = b_lr + g*16, ci = ks*2 + b_lc;
                ldsm4(bf[g], sb + 4096 + sw32(r, ci));
            }
            #pragma unroll
            for (int f = 0; f < 2; f++) {
                int r = a_lr + f*16, ci = ks*2 + a_lc;
                ldsm4(af[f], sb + sw32(r, ci));
            }
            #pragma unroll
            for (int mi = 0; mi < 2; mi++)
                #pragma unroll
                for (int ni = 0; ni < 4; ni++)
                    mma16816(acc[mi][ni], af[mi], &bf[ni >> 1][(ni & 1) * 2]);
        }
        stage = (stage + 1) & 3;
    }

    // ---- epilogue ----
    #pragma unroll
    for (int mi = 0; mi < 2; mi++) {
        #pragma unroll
        for (int half = 0; half < 2; half++) {
            int grow = rowBase + mrow + mi*16 + (lane >> 2) + half*8;
            #pragma unroll
            for (int ni = 0; ni < 4; ni++) {
                int gcol = colBase + ncol + ni*8 + (lane & 3)*2;
                float v0 = acc[mi][ni][half*2 + 0];
                float v1 = acc[mi][ni][half*2 + 1];
                if (EPI & 1) { v0 += bias[gcol]; v1 += bias[gcol + 1]; }
                if (EPI & 8) {
                    int pbi = (grow & 511)*128 + (gcol & 127);
                    v0 += g_PE[pbi]; v1 += g_PE[pbi + 1];
                }
                long oidx = (long)grow * ldc + gcol;
                if (EPI & 2) {
                    __half2 rr = *(const __half2*)(res + oidx);
                    v0 += __low2float(rr); v1 += __high2float(rr);
                }
                if (EPI & 4) { v0 = geluf(v0); v1 = geluf(v1); }
                if (!(EPI & 16)) {
                    float2 o; o.x = v0; o.y = v1;
                    *(float2*)(C + oidx) = o;
                }
                if (WRB) {
                    *(uint32_t*)(Cf + oidx) =
                        pack2h(__float2half_rn(v0), __float2half_rn(v1));
                }
                if (WRT) {   // transposed (b, d, l) fp16 write
                    long tb = (long)(grow >> 9)*65536 + (long)(gcol & 127)*512
                              + (grow & 511);
                    g_QT[tb]       = __float2half_rn(v0);
                    g_QT[tb + 512] = __float2half_rn(v1);
                }
            }
        }
    }
}

// ---------------- complex mode mixing (fp32 in, fp16 out) ------------------
__global__ void k_mix(const float* __restrict__ fwr,
                      const float* __restrict__ fwi, int layer) {
    int p = blockIdx.x * 4 + (threadIdx.x >> 6);   // pair 0..1023
    int m = threadIdx.x & 63;
    int b = p >> 3, hh = p & 7;
    const float* wr = fwr + (size_t)((layer*H_ + hh)*E_*E_) * 64;
    const float* wi = fwi + (size_t)((layer*H_ + hh)*E_*E_) * 64;
    float sr[E_], si[E_];
    #pragma unroll
    for (int o = 0; o < E_; o++) { sr[o] = 0.f; si[o] = 0.f; }
    const float* Fb = g_F + (b*128 + hh*16) * 128;
    #pragma unroll
    for (int e = 0; e < E_; e++) {
        float fre = Fb[e*128 + m];
        float fim = Fb[e*128 + 64 + m];
        #pragma unroll
        for (int o = 0; o < E_; o++) {
            float cr = wr[(e*E_ + o)*64 + m];
            float ci = wi[(e*E_ + o)*64 + m];
            sr[o] += fre*cr - fim*ci;
            si[o] += fre*ci + fim*cr;
        }
    }
    int base = (b*128 + hh*16) * 128;
    #pragma unroll
    for (int o = 0; o < E_; o++) {
        g_S[base + o*128 + m]      = __float2half_rn(sr[o]);
        g_S[base + o*128 + 64 + m] = __float2half_rn(si[o]);
    }
}

// ---------------- series_decomp: fp32 in, fp16 out --------------------------
__global__ void k_movsub(const float* __restrict__ X, __half* __restrict__ Oh) {
    __shared__ float sh[88 * 128];
    int b = blockIdx.x, t0 = blockIdx.y * 64;
    int d = threadIdx.x;
    const float* Xb = X + b*65536;
    #pragma unroll 4
    for (int r = 0; r < 88; r++) {
        int t = t0 + r - 12;
        t = max(0, min(511, t));
        sh[r*128 + d] = Xb[t*128 + d];
    }
    float s = 0.f;
    #pragma unroll 4
    for (int r = 0; r < 88; r++) { s += sh[r*128 + d]; sh[r*128 + d] = s; }
    #pragma unroll 4
    for (int tt = 0; tt < 64; tt++) {
        int r = tt + 12;
        float hi = sh[(r+12)*128 + d];
        float lo = (r >= 13) ? sh[(r-13)*128 + d] : 0.f;
        float v = Xb[(t0+tt)*128 + d] - (hi - lo) * (1.0f/25.0f);
        Oh[b*65536 + (t0+tt)*128 + d] = __float2half_rn(v);
    }
}

// ---------------- LayerNorm (fp16 in/out) + fused column-sum ----------------
__global__ void k_ln(const __half* __restrict__ X, const float* __restrict__ g,
                     const float* __restrict__ be, __half* __restrict__ Out) {
    __shared__ float cm[128];
    int row  = blockIdx.x*8 + (threadIdx.x >> 5);
    int lane = threadIdx.x & 31;
    if (threadIdx.x < 128) cm[threadIdx.x] = 0.f;
    __syncthreads();
    const __half* xr = X + (size_t)row * 128;
    float v[4];
    float s = 0.f;
    #pragma unroll
    for (int i = 0; i < 4; i++) { v[i] = __half2float(xr[lane + i*32]); s += v[i]; }
    #pragma unroll
    for (int o = 16; o > 0; o >>= 1) s += __shfl_xor_sync(0xffffffffu, s, o);
    float mu = s * (1.0f/128.0f);
    float q = 0.f;
    #pragma unroll
    for (int i = 0; i < 4; i++) { float dl = v[i] - mu; q += dl*dl; }
    #pragma unroll
    for (int o = 16; o > 0; o >>= 1) q += __shfl_xor_sync(0xffffffffu, q, o);
    float rstd = rsqrtf(q * (1.0f/128.0f) + 1e-5f);
    __half* orow = Out + (size_t)row * 128;
    #pragma unroll
    for (int i = 0; i < 4; i++) {
        int d = lane + i*32;
        float o = (v[i] - mu) * rstd * g[d] + be[d];
        orow[d] = __float2half_rn(o);
        atomicAdd(&cm[d], o);
    }
    __syncthreads();
    if (threadIdx.x < 128) {
        int b = row >> 9;
        atomicAdd(&g_CM[b*128 + threadIdx.x], cm[threadIdx.x]);
    }
}

// ---------------- final: gelu(hn - colmean) * mark . pw --------------------
__global__ void k_final(const __half* __restrict__ HN, const float* __restrict__ pw,
                        float* __restrict__ out) {
    int b = blockIdx.x, tid = threadIdx.x;
    int loc0 = blockIdx.y*8192;
    int base = b*65536 + loc0;
    float s = 0.f;
    for (int i = tid; i < 8192; i += 256) {
        int gi = base + i;
        float v = __half2float(HN[gi]) - g_CM[b*128 + (gi & 127)] * (1.0f/512.0f);
        s += geluf(v) * __half2float(g_MarkH[gi]) * pw[loc0 + i];
    }
    __shared__ float red[256];
    red[tid] = s; __syncthreads();
    #pragma unroll
    for (int o = 128; o > 0; o >>= 1) {
        if (tid < o) red[tid] += red[tid + o];
        __syncthreads();
    }
    if (tid == 0) atomicAdd(&out[b], red[0]);
}

// ---------------- host orchestration ----------------
#define SMB 49152

extern "C" void kernel_launch(void* const* d_in, const int* in_sizes, int n_in,
                              void* d_out, int out_size) {
    const float* x_enc  = (const float*)d_in[0];
    const float* mark   = (const float*)d_in[1];
    const float* conv_w = (const float*)d_in[4];
    const float* Wq     = (const float*)d_in[5];
    const float* bq     = (const float*)d_in[6];
    const float* Wo     = (const float*)d_in[7];
    const float* bo     = (const float*)d_in[8];
    const float* fwr    = (const float*)d_in[9];
    const float* fwi    = (const float*)d_in[10];
    const float* W1     = (const float*)d_in[11];
    const float* W2     = (const float*)d_in[12];
    const float* ln_g   = (const float*)d_in[13];
    const float* ln_b   = (const float*)d_in[14];
    const float* pw     = (const float*)d_in[15];
    const float* pb     = (const float*)d_in[16];
    float* out = (float*)d_out;

    cudaFuncSetAttribute(k_tgemm<24,1,0>, cudaFuncAttributeMaxDynamicSharedMemorySize, SMB);
    cudaFuncSetAttribute(k_tgemm<17,0,1>, cudaFuncAttributeMaxDynamicSharedMemorySize, SMB);
    cudaFuncSetAttribute(k_tgemm<0,0,0>,  cudaFuncAttributeMaxDynamicSharedMemorySize, SMB);
    cudaFuncSetAttribute(k_tgemm<16,1,0>, cudaFuncAttributeMaxDynamicSharedMemorySize, SMB);
    cudaFuncSetAttribute(k_tgemm<3,0,0>,  cudaFuncAttributeMaxDynamicSharedMemorySize, SMB);
    cudaFuncSetAttribute(k_tgemm<20,1,0>, cudaFuncAttributeMaxDynamicSharedMemorySize, SMB);
    cudaFuncSetAttribute(k_tgemm<2,0,0>,  cudaFuncAttributeMaxDynamicSharedMemorySize, SMB);

    float *pT2, *pF;
    cudaGetSymbolAddress((void**)&pT2,  g_T2);
    cudaGetSymbolAddress((void**)&pF,   g_F);
    __half *x16,*hx,*q16,*qt,*s16,*u16,*hn;
    cudaGetSymbolAddress((void**)&x16, g_X);
    cudaGetSymbolAddress((void**)&hx,  g_Hx);
    cudaGetSymbolAddress((void**)&q16, g_Q);
    cudaGetSymbolAddress((void**)&qt,  g_QT);
    cudaGetSymbolAddress((void**)&s16, g_S);
    cudaGetSymbolAddress((void**)&u16, g_U);
    cudaGetSymbolAddress((void**)&hn,  g_HN);
    __half *cw,*fb,*ib,*wq,*wo,*w1,*w2;
    cudaGetSymbolAddress((void**)&cw, g_cw);
    cudaGetSymbolAddress((void**)&fb, g_fb);
    cudaGetSymbolAddress((void**)&ib, g_ib);
    cudaGetSymbolAddress((void**)&wq, g_wq);
    cudaGetSymbolAddress((void**)&wo, g_wo);
    cudaGetSymbolAddress((void**)&w1, g_w1);
    cudaGetSymbolAddress((void**)&w2, g_w2);

    k_prep<<<256, 256>>>(conv_w, Wq, Wo, W1, W2, pb, out);
    k_transpose<<<dim3(16,4,128), dim3(32,8)>>>(x_enc, mark);

    // TokenEmbedding conv (K=384) + PE -> fp16 H
    k_tgemm<24,1,0><<<dim3(1024,1), 256, SMB>>>(
        x16, cw, nullptr, nullptr, nullptr, hx, 384, 128, 9, LP_*128, 128);

    for (int l = 0; l < 2; l++) {
        // Q = H @ Wq + bq -> transposed fp16 (b,d,l) directly
        k_tgemm<17,0,1><<<dim3(1024,1), 256, SMB>>>(
            hx, wq + l*16384, bq + l*128, nullptr, nullptr, nullptr,
            128, 128, 30, 0, 128);
        // forward DFT -> fp32 F
        k_tgemm<0,0,0><<<dim3(256,1), 256, SMB>>>(
            qt, fb, nullptr, nullptr, pF, nullptr, 512, 128, 30, 0, 512);
        // complex mode mixing -> fp16 S
        k_mix<<<256, 256>>>(fwr, fwi, l);
        // inverse DFT -> fp16 flat (== scrambled view(B,L,-1))
        k_tgemm<16,1,0><<<dim3(256,4), 256, SMB>>>(
            s16, ib, nullptr, nullptr, nullptr, q16, 128, 512, 30, 0, 128);
        // out proj + bias + residual(fp16 H) -> fp32 T2
        k_tgemm<3,0,0><<<dim3(1024,1), 256, SMB>>>(
            q16, wo + l*16384, bo + l*128, hx, pT2, nullptr,
            128, 128, 30, 0, 128);
        // decomp1 -> fp16 H
        k_movsub<<<dim3(128,8), 128>>>(pT2, hx);
        // FFN up + gelu -> fp16 U
        k_tgemm<20,1,0><<<dim3(1024,4), 256, SMB>>>(
            hx, w1 + l*65536, nullptr, nullptr, nullptr, u16,
            128, 512, 30, 0, 128);
        // FFN down + residual(fp16 H) -> fp32 T2
        k_tgemm<2,0,0><<<dim3(1024,1), 256, SMB>>>(
            u16, w2 + l*65536, nullptr, hx, pT2, nullptr,
            512, 128, 30, 0, 512);
        // decomp2 -> fp16 H
        k_movsub<<<dim3(128,8), 128>>>(pT2, hx);
    }

    k_ln<<<8192, 256>>>(hx, ln_g, ln_b, hn);
    k_final<<<dim3(128,8), 256>>>(hn, pw, out);
}

// round 13
// speedup vs baseline: 1.2883x; 1.0138x over previous
#include <cuda_runtime.h>
#include <cuda_fp16.h>
#include <math.h>
#include <stdint.h>

#define B_    128
#define L_    512
#define D_    128
#define H_    8
#define E_    16
#define DFF_  512
#define LP_   514

// ---------------- fp32 scratch ----------------
__device__ float g_T2 [B_*L_*D_];
__device__ float g_F  [B_*D_*128];
__device__ float g_PE [512*128];
__device__ float g_CM [B_*D_];

// ---------------- fp16 scratch ----------------
__device__ __half g_MarkH[B_*L_*D_];
__device__ __half g_X [B_*LP_*D_];
__device__ __half g_Hx[B_*L_*D_];
__device__ __half g_Q [B_*L_*D_];
__device__ __half g_QT[B_*L_*D_];
__device__ __half g_S [B_*D_*128];
__device__ __half g_U [B_*L_*DFF_];
__device__ __half g_HN[B_*L_*D_];

// ---------------- fp16 weights, [N, K] row-major ----------------
__device__ __half g_cw[128*384];
__device__ __half g_fb[128*512];
__device__ __half g_ib[512*128];
__device__ __half g_wq[2*128*128];
__device__ __half g_wo[2*128*128];
__device__ __half g_w1[2*512*128];
__device__ __half g_w2[2*128*512];

__device__ __forceinline__ float geluf(float v) {
    return 0.5f * v * (1.0f + erff(v * 0.7071067811865476f));
}
__device__ __forceinline__ uint32_t pack2h(__half a, __half b) {
    return (uint32_t)__half_as_ushort(a) | ((uint32_t)__half_as_ushort(b) << 16);
}
__device__ __forceinline__ uint32_t smem_u32(const void* p) {
    uint32_t a;
    asm("{ .reg .u64 t; cvta.to.shared.u64 t, %1; cvt.u32.u64 %0, t; }" : "=r"(a) : "l"(p));
    return a;
}
__device__ __forceinline__ void ldsm4(uint32_t* r, uint32_t a) {
    asm volatile("ldmatrix.sync.aligned.m8n8.x4.shared.b16 {%0,%1,%2,%3}, [%4];"
        : "=r"(r[0]), "=r"(r[1]), "=r"(r[2]), "=r"(r[3]) : "r"(a));
}
__device__ __forceinline__ void mma16816(float* c, const uint32_t* a, const uint32_t* b) {
    asm volatile(
        "mma.sync.aligned.m16n8k16.row.col.f32.f16.f16.f32 "
        "{%0,%1,%2,%3}, {%4,%5,%6,%7}, {%8,%9}, {%0,%1,%2,%3};"
        : "+f"(c[0]), "+f"(c[1]), "+f"(c[2]), "+f"(c[3])
        : "r"(a[0]), "r"(a[1]), "r"(a[2]), "r"(a[3]), "r"(b[0]), "r"(b[1]));
}
#define CP16(d, s)   asm volatile("cp.async.cg.shared.global [%0], [%1], 16;" :: "r"(d), "l"(s))
#define CPCOMMIT()   asm volatile("cp.async.commit_group;" ::: "memory")
#define CPWAIT2()    asm volatile("cp.async.wait_group 2;" ::: "memory")

// tile row = 32 halves = 64B = 4x16B chunks; swizzle chunk ^= (row>>1)&3
__device__ __forceinline__ uint32_t sw32(int row, int ch) {
    return (uint32_t)(row * 64) + (uint32_t)(((ch ^ ((row >> 1) & 3)) << 4));
}

// ---------------- prep: weights -> fp16 [N,K]; PE; zero CM; out=pb ---------
__global__ void k_prep(const float* __restrict__ conv_w, const float* __restrict__ Wq,
                       const float* __restrict__ Wo, const float* __restrict__ W1,
                       const float* __restrict__ W2, const float* __restrict__ pb,
                       float* __restrict__ out) {
    int idx = blockIdx.x * 256 + threadIdx.x;   // 65536 total
    if (idx < 49152) {
        int n = idx / 384, k = idx - n*384;
        int s = k >> 7, din = k & 127;
        g_cw[idx] = __float2half_rn(conv_w[n*384 + din*3 + s]);
    }
    if (idx < B_*D_) g_CM[idx] = 0.f;
    if (idx < B_)    out[idx] = pb[0];
    {   // forward DFT basis: N=128 (coeff), K=512 (t)
        int n = idx >> 9, t = idx & 511, m = n & 63;
        float x = (float)(m * t) * (1.0f/256.0f);
        float v = (n < 64) ? cospif(x) : -sinpif(x);
        g_fb[idx] = __float2half_rn(v);
    }
    {   // inverse DFT basis: N=512 (t), K=128 (coeff)
        int t = idx >> 7, n = idx & 127, m = n & 63;
        float x = (float)(m * t) * (1.0f/256.0f);
        float v;
        if (n == 0)       v = 1.0f/512.0f;
        else if (n < 64)  v = cospif(x) * (2.0f/512.0f);
        else if (n == 64) v = 0.0f;
        else              v = -sinpif(x) * (2.0f/512.0f);
        g_ib[idx] = __float2half_rn(v);
    }
    #pragma unroll
    for (int ly = 0; ly < 2; ly++) {
        if (idx < 16384) {
            int n = idx >> 7, k = idx & 127;
            g_wq[ly*16384 + idx] = __float2half_rn(Wq[ly*16384 + k*128 + n]);
            g_wo[ly*16384 + idx] = __float2half_rn(Wo[ly*16384 + k*128 + n]);
        }
        {
            int n = idx >> 7, k = idx & 127;
            g_w1[ly*65536 + idx] = __float2half_rn(W1[ly*65536 + k*512 + n]);
        }
        {
            int n = idx >> 9, k = idx & 511;
            g_w2[ly*65536 + idx] = __float2half_rn(W2[ly*65536 + k*128 + n]);
        }
    }
    {
        int t = idx >> 7, d = idx & 127;
        int i2 = d & ~1;
        float div = expf((float)i2 * (-9.210340371976184f / 128.0f));
        float a = (float)t * div;
        g_PE[idx] = (d & 1) ? cosf(a) : sinf(a);
    }
}

// ---------------- input transpose + circular edges (fused) -----------------
__global__ void k_transpose(const float* __restrict__ x_enc,
                            const float* __restrict__ mark) {
    __shared__ float tile [32][33];
    __shared__ float tileM[32][33];
    int b = blockIdx.z;
    int d0 = blockIdx.y * 32, l0 = blockIdx.x * 32;
    int tx = threadIdx.x, ty = threadIdx.y;
    const float* xb = x_enc + b*65536;
    const float* mb = mark  + b*65536;
    #pragma unroll
    for (int i = ty; i < 32; i += 8) {
        tile [i][tx] = xb[(d0+i)*512 + l0 + tx];
        tileM[i][tx] = mb[(d0+i)*512 + l0 + tx];
    }
    __syncthreads();
    #pragma unroll
    for (int i = ty; i < 32; i += 8) {
        int oi = b*LP_*128 + (l0+i+1)*128 + d0+tx;
        g_X[oi] = __float2half_rn(tile[tx][i]);
        g_MarkH[b*65536 + (l0+i)*128 + d0+tx] = __float2half_rn(tileM[tx][i]);
    }
    if (ty == 0) {
        if (blockIdx.x == 0)
            g_X[b*LP_*128 + 513*128 + d0+tx] = __float2half_rn(tile[tx][0]);
        if (blockIdx.x == 15)
            g_X[b*LP_*128 + d0+tx] = __float2half_rn(tile[tx][31]);
    }
}

// ---------------- fp16 HMMA GEMM, cp.async 4-stage, K-chunk 32 --------------
// CTA tile 64(M) x 128(N); 8 warps of 32x32; 4 CTAs/SM.
// EPI bits: 1=+bias[col], 2=+res(fp16), 4=gelu, 8=+PE, 16=skip fp32 C store
// WRB: write fp16 result to Cf (flat).  WRT: smem-staged transposed write to g_QT.
template<int EPI, int WRB, int WRT>
__global__ void __launch_bounds__(256, 4) k_tgemm(
    const __half* __restrict__ A, const __half* __restrict__ B,
    const float* __restrict__ bias, const __half* __restrict__ res,
    float* __restrict__ C, __half* __restrict__ Cf,
    int K, int ldc, int absh, int abstr, int arstr)
{
    extern __shared__ char sm[];
    const uint32_t sU = smem_u32(sm);
    const int tid = threadIdx.x, wid = tid >> 5, lane = tid & 31;
    const int rowBase = blockIdx.x * 64, colBase = blockIdx.y * 128;
    const int amask = (1 << absh) - 1;

    float acc[2][4][4];
    #pragma unroll
    for (int i = 0; i < 2; i++)
        #pragma unroll
        for (int j = 0; j < 4; j++)
            #pragma unroll
            for (int q = 0; q < 4; q++) acc[i][j][q] = 0.f;

    const int nc = K >> 5;

    const int a_row = tid >> 2, a_ch = tid & 3;
    const uint32_t a_sw = sw32(a_row, a_ch);
    int a_rg = rowBase + a_row;
    const long a_base = (long)(a_rg >> absh)*abstr + (long)(a_rg & amask)*arstr + a_ch*8;
    const int b_row0 = tid >> 2, b_row1 = 64 + (tid >> 2);
    const uint32_t b_sw0 = sw32(b_row0, a_ch), b_sw1 = sw32(b_row1, a_ch);
    const long b_base0 = (long)(colBase + b_row0)*K + a_ch*8;
    const long b_base1 = (long)(colBase + b_row1)*K + a_ch*8;

    auto load_chunk = [&](int stage, int k0) {
        uint32_t sb = sU + stage * 12288;
        CP16(sb +        a_sw, A + a_base + k0);
        CP16(sb + 4096 + b_sw0, B + b_base0 + k0);
        CP16(sb + 4096 + b_sw1, B + b_base1 + k0);
    };

    load_chunk(0, 0);  CPCOMMIT();
    load_chunk(1, 32); CPCOMMIT();
    load_chunk(2, 64); CPCOMMIT();

    const int mrow = (wid & 1) * 32;
    const int ncol = (wid >> 1) * 32;
    const int a_lr  = mrow + (lane & 15);
    const int a_lc  = lane >> 4;
    const int b_lr  = ncol + (lane & 7) + ((lane & 16) ? 8 : 0);
    const int b_lc  = (lane >> 3) & 1;
    int stage = 0;

    for (int c = 0; c < nc; c++) {
        CPWAIT2();
        __syncthreads();
        if (c + 3 < nc) load_chunk((stage + 3) & 3, (c + 3) * 32);
        CPCOMMIT();

        uint32_t sb = sU + stage * 12288;
        #pragma unroll
        for (int ks = 0; ks < 2; ks++) {
            uint32_t af[2][4], bf[2][4];
            #pragma unroll
            for (int g = 0; g < 2; g++) {
                int r = b_lr + g*16, ci = ks*2 + b_lc;
                ldsm4(bf[g], sb + 4096 + sw32(r, ci));
            }
            #pragma unroll
            for (int f = 0; f < 2; f++) {
                int r = a_lr + f*16, ci = ks*2 + a_lc;
                ldsm4(af[f], sb + sw32(r, ci));
            }
            #pragma unroll
            for (int mi = 0; mi < 2; mi++)
                #pragma unroll
                for (int ni = 0; ni < 4; ni++)
                    mma16816(acc[mi][ni], af[mi], &bf[ni >> 1][(ni & 1) * 2]);
        }
        stage = (stage + 1) & 3;
    }

    if (WRT) __syncthreads();   // reclaim pipeline smem for transpose staging
    __half* tst = (__half*)(sm + wid * 2176);   // 32x33 halves per warp

    // ---- epilogue ----
    #pragma unroll
    for (int mi = 0; mi < 2; mi++) {
        #pragma unroll
        for (int half = 0; half < 2; half++) {
            int grow = rowBase + mrow + mi*16 + (lane >> 2) + half*8;
            #pragma unroll
            for (int ni = 0; ni < 4; ni++) {
                int gcol = colBase + ncol + ni*8 + (lane & 3)*2;
                float v0 = acc[mi][ni][half*2 + 0];
                float v1 = acc[mi][ni][half*2 + 1];
                if (EPI & 1) { v0 += bias[gcol]; v1 += bias[gcol + 1]; }
                if (EPI & 8) {
                    int pbi = (grow & 511)*128 + (gcol & 127);
                    v0 += g_PE[pbi]; v1 += g_PE[pbi + 1];
                }
                long oidx = (long)grow * ldc + gcol;
                if (EPI & 2) {
                    __half2 rr = *(const __half2*)(res + oidx);
                    v0 += __low2float(rr); v1 += __high2float(rr);
                }
                if (EPI & 4) { v0 = geluf(v0); v1 = geluf(v1); }
                if (!(EPI & 16)) {
                    float2 o; o.x = v0; o.y = v1;
                    *(float2*)(C + oidx) = o;
                }
                if (WRB) {
                    *(uint32_t*)(Cf + oidx) =
                        pack2h(__float2half_rn(v0), __float2half_rn(v1));
                }
                if (WRT) {
                    int cl = ni*8 + (lane & 3)*2;
                    int rl = mi*16 + (lane >> 2) + half*8;
                    tst[cl*33 + rl]     = __float2half_rn(v0);
                    tst[(cl+1)*33 + rl] = __float2half_rn(v1);
                }
            }
        }
    }
    if (WRT) {
        __syncwarp();
        int bI = rowBase >> 9;
        int tb = (rowBase & 511) + mrow + (lane & 7)*4;
        #pragma unroll
        for (int rep = 0; rep < 8; rep++) {
            int dl = rep*4 + (lane >> 3);
            int tl = (lane & 7)*4;
            __half h0 = tst[dl*33 + tl],     h1 = tst[dl*33 + tl + 1];
            __half h2 = tst[dl*33 + tl + 2], h3 = tst[dl*33 + tl + 3];
            uint2 o; o.x = pack2h(h0, h1); o.y = pack2h(h2, h3);
            int dg = (colBase + ncol + dl) & 127;
            *(uint2*)(g_QT + bI*65536 + dg*512 + tb) = o;
        }
    }
}

// ---------------- complex mode mixing (fp32 in, fp16 out) ------------------
__global__ void k_mix(const float* __restrict__ fwr,
                      const float* __restrict__ fwi, int layer) {
    int p = blockIdx.x * 4 + (threadIdx.x >> 6);
    int m = threadIdx.x & 63;
    int b = p >> 3, hh = p & 7;
    const float* wr = fwr + (size_t)((layer*H_ + hh)*E_*E_) * 64;
    const float* wi = fwi + (size_t)((layer*H_ + hh)*E_*E_) * 64;
    float sr[E_], si[E_];
    #pragma unroll
    for (int o = 0; o < E_; o++) { sr[o] = 0.f; si[o] = 0.f; }
    const float* Fb = g_F + (b*128 + hh*16) * 128;
    #pragma unroll
    for (int e = 0; e < E_; e++) {
        float fre = Fb[e*128 + m];
        float fim = Fb[e*128 + 64 + m];
        #pragma unroll
        for (int o = 0; o < E_; o++) {
            float cr = wr[(e*E_ + o)*64 + m];
            float ci = wi[(e*E_ + o)*64 + m];
            sr[o] += fre*cr - fim*ci;
            si[o] += fre*ci + fim*cr;
        }
    }
    int base = (b*128 + hh*16) * 128;
    #pragma unroll
    for (int o = 0; o < E_; o++) {
        g_S[base + o*128 + m]      = __float2half_rn(sr[o]);
        g_S[base + o*128 + 64 + m] = __float2half_rn(si[o]);
    }
}

// ---------------- series_decomp: fp32 in, fp16 out --------------------------
__global__ void k_movsub(const float* __restrict__ X, __half* __restrict__ Oh) {
    __shared__ float sh[88 * 128];
    int b = blockIdx.x, t0 = blockIdx.y * 64;
    int d = threadIdx.x;
    const float* Xb = X + b*65536;
    #pragma unroll 4
    for (int r = 0; r < 88; r++) {
        int t = t0 + r - 12;
        t = max(0, min(511, t));
        sh[r*128 + d] = Xb[t*128 + d];
    }
    float s = 0.f;
    #pragma unroll 4
    for (int r = 0; r < 88; r++) { s += sh[r*128 + d]; sh[r*128 + d] = s; }
    #pragma unroll 4
    for (int tt = 0; tt < 64; tt++) {
        int r = tt + 12;
        float hi = sh[(r+12)*128 + d];
        float lo = (r >= 13) ? sh[(r-13)*128 + d] : 0.f;
        float v = Xb[(t0+tt)*128 + d] - (hi - lo) * (1.0f/25.0f);
        Oh[b*65536 + (t0+tt)*128 + d] = __float2half_rn(v);
    }
}

// ---------------- fused decomp2 + LayerNorm + colmean (final layer) --------
// dyn smem: cumsum 88*128 | seasonal 8*128 | cm 128  = 49664 B
__global__ void k_msln(const float* __restrict__ X, const float* __restrict__ g,
                       const float* __restrict__ be, __half* __restrict__ Out) {
    extern __shared__ float dsm[];
    float* sh = dsm;                 // 88*128 cumsum
    float* s2 = dsm + 88*128;        // 8*128 seasonal group
    float* cm = dsm + 96*128;        // 128 colsum
    int b = blockIdx.x, t0 = blockIdx.y * 64;
    int d = threadIdx.x;
    int wid = d >> 5, lane = d & 31;
    const float* Xb = X + b*65536;
    #pragma unroll 4
    for (int r = 0; r < 88; r++) {
        int t = t0 + r - 12;
        t = max(0, min(511, t));
        sh[r*128 + d] = Xb[t*128 + d];
    }
    float s = 0.f;
    #pragma unroll 4
    for (int r = 0; r < 88; r++) { s += sh[r*128 + d]; sh[r*128 + d] = s; }
    cm[d] = 0.f;
    __syncthreads();

    for (int gix = 0; gix < 8; gix++) {
        #pragma unroll
        for (int k = 0; k < 8; k++) {
            int tt = gix*8 + k, r = tt + 12;
            float hi = sh[(r+12)*128 + d];
            float lo = (r >= 13) ? sh[(r-13)*128 + d] : 0.f;
            s2[k*128 + d] = Xb[(t0+tt)*128 + d] - (hi - lo) * (1.0f/25.0f);
        }
        __syncthreads();
        #pragma unroll
        for (int rr = 0; rr < 2; rr++) {
            int k = wid*2 + rr;
            int trow = t0 + gix*8 + k;
            float v[4];
            float su = 0.f;
            #pragma unroll
            for (int i = 0; i < 4; i++) { v[i] = s2[k*128 + lane + i*32]; su += v[i]; }
            #pragma unroll
            for (int o = 16; o > 0; o >>= 1) su += __shfl_xor_sync(0xffffffffu, su, o);
            float mu = su * (1.0f/128.0f);
            float q = 0.f;
            #pragma unroll
            for (int i = 0; i < 4; i++) { float dl = v[i] - mu; q += dl*dl; }
            #pragma unroll
            for (int o = 16; o > 0; o >>= 1) q += __shfl_xor_sync(0xffffffffu, q, o);
            float rstd = rsqrtf(q * (1.0f/128.0f) + 1e-5f);
            __half* orow = Out + (size_t)(b*512 + trow) * 128;
            #pragma unroll
            for (int i = 0; i < 4; i++) {
                int dd = lane + i*32;
                float o = (v[i] - mu) * rstd * g[dd] + be[dd];
                orow[dd] = __float2half_rn(o);
                atomicAdd(&cm[dd], o);
            }
        }
        __syncthreads();
    }
    atomicAdd(&g_CM[b*128 + d], cm[d]);
}

// ---------------- final: gelu(hn - colmean) * mark . pw --------------------
__global__ void k_final(const __half* __restrict__ HN, const float* __restrict__ pw,
                        float* __restrict__ out) {
    int b = blockIdx.x, tid = threadIdx.x;
    int loc0 = blockIdx.y*8192;
    int base = b*65536 + loc0;
    float s = 0.f;
    for (int i = tid*2; i < 8192; i += 512) {
        int gi = base + i;
        __half2 h  = *(const __half2*)(HN + gi);
        __half2 mk = *(const __half2*)(g_MarkH + gi);
        float2 pp  = *(const float2*)(pw + loc0 + i);
        int dbase = b*128 + (gi & 127);
        float v0 = __low2float(h)  - g_CM[dbase]     * (1.0f/512.0f);
        float v1 = __high2float(h) - g_CM[dbase + 1] * (1.0f/512.0f);
        s += geluf(v0) * __low2float(mk)  * pp.x;
        s += geluf(v1) * __high2float(mk) * pp.y;
    }
    __shared__ float red[256];
    red[tid] = s; __syncthreads();
    #pragma unroll
    for (int o = 128; o > 0; o >>= 1) {
        if (tid < o) red[tid] += red[tid + o];
        __syncthreads();
    }
    if (tid == 0) atomicAdd(&out[b], red[0]);
}

// ---------------- host orchestration ----------------
#define SMB    49152
#define SMLN   49664

extern "C" void kernel_launch(void* const* d_in, const int* in_sizes, int n_in,
                              void* d_out, int out_size) {
    const float* x_enc  = (const float*)d_in[0];
    const float* mark   = (const float*)d_in[1];
    const float* conv_w = (const float*)d_in[4];
    const float* Wq     = (const float*)d_in[5];
    const float* bq     = (const float*)d_in[6];
    const float* Wo     = (const float*)d_in[7];
    const float* bo     = (const float*)d_in[8];
    const float* fwr    = (const float*)d_in[9];
    const float* fwi    = (const float*)d_in[10];
    const float* W1     = (const float*)d_in[11];
    const float* W2     = (const float*)d_in[12];
    const float* ln_g   = (const float*)d_in[13];
    const float* ln_b   = (const float*)d_in[14];
    const float* pw     = (const float*)d_in[15];
    const float* pb     = (const float*)d_in[16];
    float* out = (float*)d_out;

    cudaFuncSetAttribute(k_tgemm<24,1,0>, cudaFuncAttributeMaxDynamicSharedMemorySize, SMB);
    cudaFuncSetAttribute(k_tgemm<17,0,1>, cudaFuncAttributeMaxDynamicSharedMemorySize, SMB);
    cudaFuncSetAttribute(k_tgemm<0,0,0>,  cudaFuncAttributeMaxDynamicSharedMemorySize, SMB);
    cudaFuncSetAttribute(k_tgemm<16,1,0>, cudaFuncAttributeMaxDynamicSharedMemorySize, SMB);
    cudaFuncSetAttribute(k_tgemm<3,0,0>,  cudaFuncAttributeMaxDynamicSharedMemorySize, SMB);
    cudaFuncSetAttribute(k_tgemm<20,1,0>, cudaFuncAttributeMaxDynamicSharedMemorySize, SMB);
    cudaFuncSetAttribute(k_tgemm<2,0,0>,  cudaFuncAttributeMaxDynamicSharedMemorySize, SMB);
    cudaFuncSetAttribute(k_msln,          cudaFuncAttributeMaxDynamicSharedMemorySize, SMLN);

    float *pT2, *pF;
    cudaGetSymbolAddress((void**)&pT2,  g_T2);
    cudaGetSymbolAddress((void**)&pF,   g_F);
    __half *x16,*hx,*q16,*qt,*s16,*u16,*hn;
    cudaGetSymbolAddress((void**)&x16, g_X);
    cudaGetSymbolAddress((void**)&hx,  g_Hx);
    cudaGetSymbolAddress((void**)&q16, g_Q);
    cudaGetSymbolAddress((void**)&qt,  g_QT);
    cudaGetSymbolAddress((void**)&s16, g_S);
    cudaGetSymbolAddress((void**)&u16, g_U);
    cudaGetSymbolAddress((void**)&hn,  g_HN);
    __half *cw,*fb,*ib,*wq,*wo,*w1,*w2;
    cudaGetSymbolAddress((void**)&cw, g_cw);
    cudaGetSymbolAddress((void**)&fb, g_fb);
    cudaGetSymbolAddress((void**)&ib, g_ib);
    cudaGetSymbolAddress((void**)&wq, g_wq);
    cudaGetSymbolAddress((void**)&wo, g_wo);
    cudaGetSymbolAddress((void**)&w1, g_w1);
    cudaGetSymbolAddress((void**)&w2, g_w2);

    k_prep<<<256, 256>>>(conv_w, Wq, Wo, W1, W2, pb, out);
    k_transpose<<<dim3(16,4,128), dim3(32,8)>>>(x_enc, mark);

    // TokenEmbedding conv (K=384) + PE -> fp16 H
    k_tgemm<24,1,0><<<dim3(1024,1), 256, SMB>>>(
        x16, cw, nullptr, nullptr, nullptr, hx, 384, 128, 9, LP_*128, 128);

    for (int l = 0; l < 2; l++) {
        // Q = H @ Wq + bq -> transposed fp16 (b,d,l)
        k_tgemm<17,0,1><<<dim3(1024,1), 256, SMB>>>(
            hx, wq + l*16384, bq + l*128, nullptr, nullptr, nullptr,
            128, 128, 30, 0, 128);
        // forward DFT -> fp32 F
        k_tgemm<0,0,0><<<dim3(256,1), 256, SMB>>>(
            qt, fb, nullptr, nullptr, pF, nullptr, 512, 128, 30, 0, 512);
        // complex mode mixing -> fp16 S
        k_mix<<<256, 256>>>(fwr, fwi, l);
        // inverse DFT -> fp16 flat (== scrambled view(B,L,-1))
        k_tgemm<16,1,0><<<dim3(256,4), 256, SMB>>>(
            s16, ib, nullptr, nullptr, nullptr, q16, 128, 512, 30, 0, 128);
        // out proj + bias + residual(fp16 H) -> fp32 T2
        k_tgemm<3,0,0><<<dim3(1024,1), 256, SMB>>>(
            q16, wo + l*16384, bo + l*128, hx, pT2, nullptr,
            128, 128, 30, 0, 128);
        // decomp1 -> fp16 H
        k_movsub<<<dim3(128,8), 128>>>(pT2, hx);
        // FFN up + gelu -> fp16 U
        k_tgemm<20,1,0><<<dim3(1024,4), 256, SMB>>>(
            hx, w1 + l*65536, nullptr, nullptr, nullptr, u16,
            128, 512, 30, 0, 128);
        // FFN down + residual(fp16 H) -> fp32 T2
        k_tgemm<2,0,0><<<dim3(1024,1), 256, SMB>>>(
            u16, w2 + l*65536, nullptr, hx, pT2, nullptr,
            512, 128, 30, 0, 512);
        // decomp2
        if (l == 0) {
            k_movsub<<<dim3(128,8), 128>>>(pT2, hx);
        } else {
            // fused decomp2 + LayerNorm + colmean -> fp16 HN
            k_msln<<<dim3(128,8), 128, SMLN>>>(pT2, ln_g, ln_b, hn);
        }
    }

    k_final<<<dim3(128,8), 256>>>(hn, pw, out);
}